// round 6
// baseline (speedup 1.0000x reference)
#include <cuda_runtime.h>
#include <cuda_fp16.h>
#include <math.h>
#include <stdint.h>

// Problem constants
#define Bb   1024
#define Uu   8
#define Ss   50
#define Ll   200
#define Ff   4
#define Ee   32
#define Dd   128      // F*E
#define UE   256      // U*E
#define G4   512      // 4*D
#define NEGV -1000000000.0f

// ---------------- scratch (static device globals) ---------------------------
__device__ float  g_user_e[Bb * UE];          // (B,256)
__device__ float  g_user_t[Bb * UE];          // tf32-rounded copy
__device__ float  g_stx   [Bb * Ss * Dd];     // (B,50,128) tf32-rounded
__device__ float  g_xW    [Bb * Ss * G4];     // (B,50,512) x@W+b (fp32)
__device__ float  g_hs    [Bb * Ss * Dd];     // LSTM outputs (tf32-rounded)
__device__ float  g_qkv   [Bb * Ss * 384];    // fused q|k|v
__device__ float  g_att   [Bb * Ss * Dd];     // attn out, pre-Wo (tf32-rounded)
__device__ float  g_stm   [Bb * Ss * Dd];     // MHA out (post-Wo)
__device__ float  g_qvec  [Bb * Dd];
__device__ float  g_short [Bb * Dd];
__device__ float  g_long  [Bb * Dd];
__device__ __half g_Uh    [G4 * Dd];          // U^T as fp16: [n=512][k=128]
__device__ float  g_Wr    [Dd * G4];          // tf32-rounded lstm_W
__device__ float  g_Wqkv  [Dd * 384];         // tf32-rounded packed Wq|Wk|Wv
__device__ float  g_Wor   [Dd * Dd];          // tf32-rounded Wo
__device__ float  g_W1r   [UE * Dd];          // tf32-rounded W1

__device__ __forceinline__ float sigm(float x) { return 1.0f / (1.0f + __expf(-x)); }

__device__ __forceinline__ float to_tf32(float x) {
    uint32_t u;
    asm("cvt.rna.tf32.f32 %0, %1;" : "=r"(u) : "f"(x));
    return __uint_as_float(u);
}

__device__ __forceinline__ void cp16(void* smem, const void* g) {
    uint32_t s = (uint32_t)__cvta_generic_to_shared(smem);
    asm volatile("cp.async.ca.shared.global [%0], [%1], 16;" :: "r"(s), "l"(g));
}

__device__ __forceinline__ void mma_tf32(float* c, const uint32_t* a, const uint32_t* b) {
    asm volatile(
        "mma.sync.aligned.m16n8k8.row.col.f32.tf32.tf32.f32 "
        "{%0,%1,%2,%3}, {%4,%5,%6,%7}, {%8,%9}, {%0,%1,%2,%3};"
        : "+f"(c[0]), "+f"(c[1]), "+f"(c[2]), "+f"(c[3])
        : "r"(a[0]), "r"(a[1]), "r"(a[2]), "r"(a[3]), "r"(b[0]), "r"(b[1]));
}

__device__ __forceinline__ void mma_f16(float* c, const uint32_t* a, const uint32_t* b) {
    asm volatile(
        "mma.sync.aligned.m16n8k16.row.col.f32.f16.f16.f32 "
        "{%0,%1,%2,%3}, {%4,%5,%6,%7}, {%8,%9}, {%0,%1,%2,%3};"
        : "+f"(c[0]), "+f"(c[1]), "+f"(c[2]), "+f"(c[3])
        : "r"(a[0]), "r"(a[1]), "r"(a[2]), "r"(a[3]), "r"(b[0]), "r"(b[1]));
}

__device__ __forceinline__ void ldsm_x4(uint32_t& r0, uint32_t& r1, uint32_t& r2,
                                        uint32_t& r3, uint32_t addr) {
    asm volatile("ldmatrix.sync.aligned.m8n8.x4.shared.b16 {%0,%1,%2,%3}, [%4];"
                 : "=r"(r0), "=r"(r1), "=r"(r2), "=r"(r3) : "r"(addr));
}

__device__ __forceinline__ void ldsm_x2(uint32_t& r0, uint32_t& r1, uint32_t addr) {
    asm volatile("ldmatrix.sync.aligned.m8n8.x2.shared.b16 {%0,%1}, [%2];"
                 : "=r"(r0), "=r"(r1) : "r"(addr));
}

// ---------------- 1) embedding gathers --------------------------------------
__global__ void gather_kernel(const int* __restrict__ up, const int* __restrict__ stb,
                              const float* __restrict__ emb) {
    int idx = blockIdx.x * blockDim.x + threadIdx.x;
    const int n1 = Bb * UE;
    if (idx < n1) {
        int b = idx / UE, r = idx % UE;
        int u = r / Ee, e = r % Ee;
        float v = emb[up[b * Uu + u] * Ee + e];
        g_user_e[idx] = v;
        g_user_t[idx] = to_tf32(v);
    }
    int idx2 = idx - n1;
    if (idx2 >= 0 && idx2 < Bb * Ss * Dd) {
        int e = idx2 & (Ee - 1);
        int t = idx2 / Ee;            // (b*S+s)*F + f
        int f = t & (Ff - 1);
        int bs = t / Ff;              // b*S+s
        g_stx[idx2] = to_tf32(emb[stb[bs * Ff + f] * Ee + e]);
    }
}

// ---------------- 2) weight repacks ----------------------------------------
__global__ void repackU_kernel(const float* __restrict__ Uw) {
    int idx = blockIdx.x * blockDim.x + threadIdx.x;   // 65536
    if (idx >= G4 * Dd) return;
    int n = idx >> 7, k = idx & 127;
    g_Uh[idx] = __float2half(Uw[k * G4 + n]);
}

__global__ void repackW_kernel(const float* __restrict__ lstm_W,
                               const float* __restrict__ Wq,
                               const float* __restrict__ Wk,
                               const float* __restrict__ Wv,
                               const float* __restrict__ Wo,
                               const float* __restrict__ W1) {
    int idx = blockIdx.x * blockDim.x + threadIdx.x;
    if (idx < Dd * G4) {
        g_Wr[idx] = to_tf32(lstm_W[idx]);
        return;
    }
    int j = idx - Dd * G4;
    if (j < Dd * 384) {
        int k = j / 384, n = j % 384;
        float v = (n < 128) ? Wq[k * Dd + n]
                : (n < 256) ? Wk[k * Dd + (n - 128)]
                            : Wv[k * Dd + (n - 256)];
        g_Wqkv[j] = to_tf32(v);
        return;
    }
    j -= Dd * 384;
    if (j < Dd * Dd) { g_Wor[j] = to_tf32(Wo[j]); return; }
    j -= Dd * Dd;
    if (j < UE * Dd) g_W1r[j] = to_tf32(W1[j]);
}

// ---------------- tf32 tensor-core GEMM: C[M,N]=A[M,K]@W[K,N] (+bias) -------
__global__ __launch_bounds__(256, 2) void gemm_tf32(
    const float* __restrict__ A, const float* __restrict__ W,
    const float* __restrict__ bias, float* __restrict__ C,
    int M, int N, int K) {
    __shared__ float As[128][36];
    __shared__ float Bs[32][136];
    int tid = threadIdx.x;
    int lane = tid & 31, warp = tid >> 5;
    int wm = warp >> 1, wn = warp & 1;
    int g = lane >> 2, tig = lane & 3;
    int m0 = blockIdx.y * 128, n0 = blockIdx.x * 128;

    float c[2][8][4];
#pragma unroll
    for (int i = 0; i < 2; i++)
#pragma unroll
        for (int j = 0; j < 8; j++)
#pragma unroll
            for (int l = 0; l < 4; l++) c[i][j][l] = 0.f;

    for (int k0 = 0; k0 < K; k0 += 32) {
        if (k0) __syncthreads();
#pragma unroll
        for (int i = 0; i < 4; i++) {
            int idx = tid + i * 256;
            int r = idx >> 3, c4 = (idx & 7) * 4;
            cp16(&As[r][c4], &A[(m0 + r) * K + k0 + c4]);
        }
#pragma unroll
        for (int i = 0; i < 4; i++) {
            int idx = tid + i * 256;
            int r = idx >> 5, c4 = (idx & 31) * 4;
            cp16(&Bs[r][c4], &W[(k0 + r) * N + n0 + c4]);
        }
        asm volatile("cp.async.commit_group;");
        asm volatile("cp.async.wait_group 0;");
        __syncthreads();

#pragma unroll
        for (int kk = 0; kk < 32; kk += 8) {
            uint32_t a[2][4], b[8][2];
#pragma unroll
            for (int mt = 0; mt < 2; mt++) {
                int mr = wm * 32 + mt * 16;
                a[mt][0] = __float_as_uint(As[mr + g][kk + tig]);
                a[mt][1] = __float_as_uint(As[mr + g + 8][kk + tig]);
                a[mt][2] = __float_as_uint(As[mr + g][kk + tig + 4]);
                a[mt][3] = __float_as_uint(As[mr + g + 8][kk + tig + 4]);
            }
#pragma unroll
            for (int nt = 0; nt < 8; nt++) {
                int nc = wn * 64 + nt * 8 + g;
                b[nt][0] = __float_as_uint(Bs[kk + tig][nc]);
                b[nt][1] = __float_as_uint(Bs[kk + tig + 4][nc]);
            }
#pragma unroll
            for (int mt = 0; mt < 2; mt++)
#pragma unroll
                for (int nt = 0; nt < 8; nt++)
                    mma_tf32(c[mt][nt], a[mt], b[nt]);
        }
    }

#pragma unroll
    for (int mt = 0; mt < 2; mt++) {
        int row = m0 + wm * 32 + mt * 16 + g;
#pragma unroll
        for (int nt = 0; nt < 8; nt++) {
            int col = n0 + wn * 64 + nt * 8 + 2 * tig;
            float bx = 0.f, by = 0.f;
            if (bias) { bx = bias[col]; by = bias[col + 1]; }
            float2 o0 = make_float2(c[mt][nt][0] + bx, c[mt][nt][1] + by);
            float2 o1 = make_float2(c[mt][nt][2] + bx, c[mt][nt][3] + by);
            *(float2*)&C[row * N + col] = o0;
            *(float2*)&C[(row + 8) * N + col] = o1;
        }
    }
}

// ---------------- 3) LSTM: fp16 mma, 16 rows/CTA, SMEM-resident U -----------
// 64 CTAs x 16 batch rows, 512 threads (16 warps). Warp w owns n-slice
// [w*32, w*32+32). Per step per warp: 8 kt x (ldsm_x4 A + 4 x (ldsm_x2 B +
// mma m16n8k16)) -> full 16-row output used. z frags -> zbuf; epilogue:
// thread (erow=tid>>5, d0=(tid&31)*4) does fp32 gate/cell update.
#define UT_STRIDE 136          // fp16 elems per Ut row (conflict-free ldmatrix)
#define HB_STRIDE 136
#define ZB_STRIDE 520
#define LSTM_ROWS 16
#define LSTM_SMEM_BYTES (G4 * UT_STRIDE * 2 + LSTM_ROWS * HB_STRIDE * 2 + LSTM_ROWS * ZB_STRIDE * 4)

__global__ __launch_bounds__(512, 1) void lstm_mma_kernel(
    const float* __restrict__ xW, float* __restrict__ hs) {
    extern __shared__ __align__(16) char smem_raw[];
    __half* Ut   = (__half*)smem_raw;                                   // [512][136]
    __half* hbuf = (__half*)(smem_raw + G4 * UT_STRIDE * 2);            // [16][136]
    float*  zbuf = (float*)(smem_raw + G4 * UT_STRIDE * 2 + LSTM_ROWS * HB_STRIDE * 2); // [16][520]

    int tid = threadIdx.x;
    int lane = tid & 31, warp = tid >> 5;
    int b0 = blockIdx.x * LSTM_ROWS;

    // ---- load U^T into smem (cp.async), zero hbuf ----
    for (int i = tid; i < G4 * Dd / 8; i += 512) {     // 8192 16B chunks
        int n = i >> 4, c = (i & 15) * 8;
        cp16(&Ut[n * UT_STRIDE + c], &g_Uh[n * Dd + c]);
    }
    for (int i = tid; i < LSTM_ROWS * HB_STRIDE; i += 512) hbuf[i] = __float2half(0.f);
    asm volatile("cp.async.commit_group;");
    asm volatile("cp.async.wait_group 0;");
    __syncthreads();

    // ---- per-lane ldmatrix base addresses ----
    uint32_t hb_base = (uint32_t)__cvta_generic_to_shared(hbuf);
    uint32_t ut_base = (uint32_t)__cvta_generic_to_shared(Ut);
    // A (hbuf, m16k16): lanes 0-15 -> rows 0-15 @k0, lanes 16-31 -> rows 0-15 @k8
    int arow = lane & 15;
    int akofs = (lane >> 4) * 8;
    uint32_t aAddr = hb_base + (arow * HB_STRIDE + akofs) * 2;
    // B (Ut, n8k16): lanes 0-7 -> n-rows, lanes 8-15 -> k+8
    int bn = lane & 7;
    int bkofs = ((lane >> 3) & 1) * 8;
    int nw = warp * 32;
    uint32_t bAddr = ut_base + ((nw + bn) * UT_STRIDE + bkofs) * 2;

    int erow = tid >> 5, d0 = (tid & 31) * 4;          // epilogue: 16 rows x 32 d-quads
    float cc[4] = {0.f, 0.f, 0.f, 0.f};
    int gid = lane >> 2, tig = lane & 3;

    for (int step = 0; step < Ss; step++) {
        // prefetch xW gates (overlaps mma phase)
        const float* xb = xW + ((b0 + erow) * Ss + step) * G4 + d0;
        float4 xi = *(const float4*)&xb[0];
        float4 xf = *(const float4*)&xb[128];
        float4 xg = *(const float4*)&xb[256];
        float4 xo = *(const float4*)&xb[384];

        // ---- mma phase: acc[nt] = (h @ U)[16 rows, nw+nt*8 ..] ----
        float acc[4][4];
#pragma unroll
        for (int nt = 0; nt < 4; nt++)
#pragma unroll
            for (int j = 0; j < 4; j++) acc[nt][j] = 0.f;
#pragma unroll
        for (int kt = 0; kt < 8; kt++) {
            uint32_t a[4];
            ldsm_x4(a[0], a[1], a[2], a[3], aAddr + kt * 32);
#pragma unroll
            for (int nt = 0; nt < 4; nt++) {
                uint32_t b[2];
                ldsm_x2(b[0], b[1], bAddr + nt * (8 * UT_STRIDE * 2) + kt * 32);
                mma_f16(acc[nt], a, b);
            }
        }
        // dump z fragments: rows gid (c0,c1) and gid+8 (c2,c3)
#pragma unroll
        for (int nt = 0; nt < 4; nt++) {
            int col = nw + nt * 8 + 2 * tig;
            *(float2*)&zbuf[gid * ZB_STRIDE + col] = make_float2(acc[nt][0], acc[nt][1]);
            *(float2*)&zbuf[(gid + 8) * ZB_STRIDE + col] = make_float2(acc[nt][2], acc[nt][3]);
        }
        __syncthreads();

        // ---- epilogue: gates, c/h update ----
        float4 zi = *(float4*)&zbuf[erow * ZB_STRIDE + d0];
        float4 zf = *(float4*)&zbuf[erow * ZB_STRIDE + 128 + d0];
        float4 zg = *(float4*)&zbuf[erow * ZB_STRIDE + 256 + d0];
        float4 zo = *(float4*)&zbuf[erow * ZB_STRIDE + 384 + d0];
        float hv[4];
        {
            float iv[4] = {zi.x + xi.x, zi.y + xi.y, zi.z + xi.z, zi.w + xi.w};
            float fv[4] = {zf.x + xf.x, zf.y + xf.y, zf.z + xf.z, zf.w + xf.w};
            float gv[4] = {zg.x + xg.x, zg.y + xg.y, zg.z + xg.z, zg.w + xg.w};
            float ov[4] = {zo.x + xo.x, zo.y + xo.y, zo.z + xo.z, zo.w + xo.w};
#pragma unroll
            for (int j = 0; j < 4; j++) {
                cc[j] = sigm(fv[j]) * cc[j] + sigm(iv[j]) * tanhf(gv[j]);
                hv[j] = sigm(ov[j]) * tanhf(cc[j]);
            }
        }
        __half2 h01 = __floats2half2_rn(hv[0], hv[1]);
        __half2 h23 = __floats2half2_rn(hv[2], hv[3]);
        *(__half2*)&hbuf[erow * HB_STRIDE + d0]     = h01;
        *(__half2*)&hbuf[erow * HB_STRIDE + d0 + 2] = h23;
        float4 ho = make_float4(to_tf32(hv[0]), to_tf32(hv[1]),
                                to_tf32(hv[2]), to_tf32(hv[3]));
        *(float4*)&hs[((b0 + erow) * Ss + step) * Dd + d0] = ho;
        __syncthreads();
    }
}

// ---------------- 4) MHA core: one block per (b, head) ----------------------
__global__ __launch_bounds__(128) void mha_kernel() {
    int bh = blockIdx.x;
    int b = bh >> 2, h = bh & 3;
    __shared__ float qs[Ss][Ee], ks[Ss][Ee], vs[Ss][Ee];
    __shared__ float sc[Ss][52];
    int t = threadIdx.x;
    for (int idx = t; idx < Ss * Ee; idx += 128) {
        int s = idx >> 5, e = idx & 31;
        int base = (b * Ss + s) * 384 + h * Ee + e;
        qs[s][e] = g_qkv[base];
        ks[s][e] = g_qkv[base + 128];
        vs[s][e] = g_qkv[base + 256];
    }
    __syncthreads();
    const float scale = 0.17677669529663687f;  // 1/sqrt(32)
    for (int idx = t; idx < Ss * Ss; idx += 128) {
        int r = idx / Ss, c = idx % Ss;
        float a = 0.f;
#pragma unroll
        for (int e = 0; e < Ee; e++) a += qs[r][e] * ks[c][e];
        sc[r][c] = a * scale;
    }
    __syncthreads();
    if (t < Ss) {
        float mx = -3.4e38f;
        for (int c = 0; c < Ss; c++) mx = fmaxf(mx, sc[t][c]);
        float sm = 0.f;
        for (int c = 0; c < Ss; c++) { float e = __expf(sc[t][c] - mx); sc[t][c] = e; sm += e; }
        float inv = 1.f / sm;
        for (int c = 0; c < Ss; c++) sc[t][c] *= inv;
    }
    __syncthreads();
    for (int idx = t; idx < Ss * Ee; idx += 128) {
        int s = idx >> 5, e = idx & 31;
        float a = 0.f;
        for (int c = 0; c < Ss; c++) a += sc[s][c] * vs[c][e];
        g_att[(b * Ss + s) * Dd + h * Ee + e] = to_tf32(a);
    }
}

// ---------------- 5) short-term attention pooling ---------------------------
__global__ __launch_bounds__(128) void shortpool_kernel() {
    int b = blockIdx.x;
    __shared__ float qv[Dd];
    __shared__ float sc[Ss];
    int t = threadIdx.x;
    qv[t] = g_qvec[b * Dd + t];
    __syncthreads();
    if (t < Ss) {
        const float* row = &g_stm[(b * Ss + t) * Dd];
        float a = 0.f;
        for (int k = 0; k < Dd; k++) a += row[k] * qv[k];
        sc[t] = a;
    }
    __syncthreads();
    if (t == 0) {
        float mx = -3.4e38f;
        for (int s = 0; s < Ss; s++) mx = fmaxf(mx, sc[s]);
        float sm = 0.f;
        for (int s = 0; s < Ss; s++) { float e = __expf(sc[s] - mx); sc[s] = e; sm += e; }
        float inv = 1.f / sm;
        for (int s = 0; s < Ss; s++) sc[s] *= inv;
    }
    __syncthreads();
    float a = 0.f;
    for (int s = 0; s < Ss; s++) a += sc[s] * g_stm[(b * Ss + s) * Dd + t];
    g_short[b * Dd + t] = a;
}

// ---------------- 6) long-term field attention (dedup mask) -----------------
__global__ __launch_bounds__(256) void longterm_kernel(const int* __restrict__ ltb,
                                                       const float* __restrict__ emb,
                                                       const float* __restrict__ Wt,
                                                       const float* __restrict__ bt) {
    int bi = blockIdx.x;
    int b = bi >> 2, fi = bi & 3;
    __shared__ int   ids[Ll];
    __shared__ float vecs[Ll][Ee];
    __shared__ float sc[Ll];
    __shared__ float uv[Ee];
    __shared__ float part[8][Ee];
    __shared__ float red[256];
    int t = threadIdx.x;
    if (t < Ll) ids[t] = ltb[(b * Ll + t) * Ff + fi];
    __syncthreads();
    for (int idx = t; idx < Ll * Ee; idx += 256) {
        int l = idx >> 5, e = idx & 31;
        vecs[l][e] = emb[ids[l] * Ee + e];
    }
    {
        int e = t & 31, g = t >> 5;
        float a = 0.f;
        for (int k = g * 32; k < g * 32 + 32; k++)
            a += g_user_e[b * UE + k] * Wt[(fi * UE + k) * Ee + e];
        part[g][e] = a;
    }
    __syncthreads();
    if (t < Ee) {
        float a = bt[fi * Ee + t];
        for (int g = 0; g < 8; g++) a += part[g][t];
        uv[t] = a;
    }
    __syncthreads();
    if (t < Ll) {
        int mid = ids[t];
        bool keep = true;
        for (int j = 0; j < t; j++) if (ids[j] == mid) { keep = false; break; }
        float a = 0.f;
#pragma unroll
        for (int e = 0; e < Ee; e++) a += vecs[t][e] * uv[e];
        sc[t] = keep ? a : NEGV;
    }
    __syncthreads();
    red[t] = (t < Ll) ? sc[t] : -3.4e38f;
    __syncthreads();
    for (int ofs = 128; ofs >= 1; ofs >>= 1) {
        if (t < ofs) red[t] = fmaxf(red[t], red[t + ofs]);
        __syncthreads();
    }
    float mx = red[0];
    __syncthreads();
    float ev = (t < Ll) ? __expf(sc[t] - mx) : 0.f;
    if (t < Ll) sc[t] = ev;
    red[t] = ev;
    __syncthreads();
    for (int ofs = 128; ofs >= 1; ofs >>= 1) {
        if (t < ofs) red[t] += red[t + ofs];
        __syncthreads();
    }
    float inv = 1.f / red[0];
    __syncthreads();
    {
        int e = t & 31, g = t >> 5;
        float a = 0.f;
        for (int l = g; l < Ll; l += 8) a += sc[l] * vecs[l][e];
        part[g][e] = a;
    }
    __syncthreads();
    if (t < Ee) {
        float a = 0.f;
        for (int g = 0; g < 8; g++) a += part[g][t];
        g_long[b * Dd + fi * Ee + t] = a * inv;
    }
}

// ---------------- 7) final gate + mix ---------------------------------------
__global__ __launch_bounds__(128) void gate_kernel(
    const float* __restrict__ Wu, const float* __restrict__ bu,
    const float* __restrict__ Wsg, const float* __restrict__ bsg,
    const float* __restrict__ Wl, const float* __restrict__ bl,
    float* __restrict__ out) {
    int b = blockIdx.x, d = threadIdx.x;
    __shared__ float ue[UE], sh[Dd], lg[Dd];
    ue[d] = g_user_e[b * UE + d];
    ue[d + 128] = g_user_e[b * UE + 128 + d];
    sh[d] = g_short[b * Dd + d];
    lg[d] = g_long[b * Dd + d];
    __syncthreads();
    float a = bu[d] + bsg[d] + bl[d];
    for (int k = 0; k < UE; k++) a += ue[k] * Wu[k * Dd + d];
    for (int k = 0; k < Dd; k++) a += sh[k] * Wsg[k * Dd + d] + lg[k] * Wl[k * Dd + d];
    float g = sigm(a);
    out[b * Dd + d] = (1.f - g) * lg[d] + g * sh[d];
}

// ---------------- host ------------------------------------------------------
static float* sym(const void* s) {
    void* p = nullptr;
    cudaGetSymbolAddress(&p, s);
    return (float*)p;
}

extern "C" void kernel_launch(void* const* d_in, const int* in_sizes, int n_in,
                              void* d_out, int out_size) {
    const int*   up     = (const int*)d_in[0];
    const int*   stb    = (const int*)d_in[1];
    const int*   ltb    = (const int*)d_in[2];
    const float* emb    = (const float*)d_in[3];
    const float* lstm_W = (const float*)d_in[4];
    const float* lstm_U = (const float*)d_in[5];
    const float* lstm_b = (const float*)d_in[6];
    const float* Wq     = (const float*)d_in[7];
    const float* Wk     = (const float*)d_in[8];
    const float* Wv     = (const float*)d_in[9];
    const float* Wo     = (const float*)d_in[10];
    const float* W1     = (const float*)d_in[11];
    const float* b1     = (const float*)d_in[12];
    const float* Wt     = (const float*)d_in[13];
    const float* bt     = (const float*)d_in[14];
    const float* Wu     = (const float*)d_in[15];
    const float* bu     = (const float*)d_in[16];
    const float* Wsg    = (const float*)d_in[17];
    const float* bsg    = (const float*)d_in[18];
    const float* Wl     = (const float*)d_in[19];
    const float* bl     = (const float*)d_in[20];
    float* out = (float*)d_out;

    float* p_user  = sym(g_user_e);
    float* p_usert = sym(g_user_t);
    float* p_stx   = sym(g_stx);
    float* p_xW    = sym(g_xW);
    float* p_hs    = sym(g_hs);
    float* p_qkv   = sym(g_qkv);
    float* p_att   = sym(g_att);
    float* p_stm   = sym(g_stm);
    float* p_qvec  = sym(g_qvec);
    float* p_Wr    = sym(g_Wr);
    float* p_Wqkv  = sym(g_Wqkv);
    float* p_Wor   = sym(g_Wor);
    float* p_W1r   = sym(g_W1r);

    const int MBS = Bb * Ss;  // 51200

    // idempotent, every call (no static guards)
    cudaFuncSetAttribute(lstm_mma_kernel,
                         cudaFuncAttributeMaxDynamicSharedMemorySize,
                         LSTM_SMEM_BYTES);

    // 1) gathers + weight repacks
    {
        int total = Bb * UE + Bb * Ss * Dd;
        gather_kernel<<<(total + 255) / 256, 256>>>(up, stb, emb);
        repackU_kernel<<<(G4 * Dd + 255) / 256, 256>>>(lstm_U);
        int wtotal = Dd * G4 + Dd * 384 + Dd * Dd + UE * Dd;
        repackW_kernel<<<(wtotal + 255) / 256, 256>>>(lstm_W, Wq, Wk, Wv, Wo, W1);
    }
    // 2) xW = stx @ lstm_W + b   (51200 x 512 x 128) tf32
    gemm_tf32<<<dim3(G4 / 128, MBS / 128), 256>>>(p_stx, p_Wr, lstm_b, p_xW, MBS, G4, Dd);
    // 3) LSTM recurrence: fp16 mma, 64 CTAs x 16 rows, SMEM-resident U
    lstm_mma_kernel<<<Bb / LSTM_ROWS, 512, LSTM_SMEM_BYTES>>>(p_xW, p_hs);
    // 4) fused QKV projection (51200 x 384 x 128) tf32
    gemm_tf32<<<dim3(384 / 128, MBS / 128), 256>>>(p_hs, p_Wqkv, nullptr, p_qkv, MBS, 384, Dd);
    // 5) attention core + output projection
    mha_kernel<<<Bb * Ff, 128>>>();
    gemm_tf32<<<dim3(Dd / 128, MBS / 128), 256>>>(p_att, p_Wor, nullptr, p_stm, MBS, Dd, Dd);
    // 6) pooling query (tf32) + short-term pooling
    gemm_tf32<<<dim3(Dd / 128, Bb / 128), 256>>>(p_usert, p_W1r, b1, p_qvec, Bb, Dd, UE);
    shortpool_kernel<<<Bb, 128>>>();
    // 7) long-term field attention
    longterm_kernel<<<Bb * Ff, 256>>>(ltb, emb, Wt, bt);
    // 8) gate + mix -> out
    gate_kernel<<<Bb, 128>>>(Wu, bu, Wsg, bsg, Wl, bl, out);
}

// round 7
// speedup vs baseline: 1.0400x; 1.0400x over previous
#include <cuda_runtime.h>
#include <cuda_fp16.h>
#include <math.h>
#include <stdint.h>

// Problem constants
#define Bb   1024
#define Uu   8
#define Ss   50
#define Ll   200
#define Ff   4
#define Ee   32
#define Dd   128      // F*E
#define UE   256      // U*E
#define G4   512      // 4*D
#define NEGV -1000000000.0f

// ---------------- scratch (static device globals) ---------------------------
__device__ float  g_user_e[Bb * UE];          // (B,256)
__device__ float  g_user_t[Bb * UE];          // tf32-rounded copy
__device__ float  g_stx   [Bb * Ss * Dd];     // (B,50,128) tf32-rounded
__device__ float  g_xW    [Bb * Ss * G4];     // (B,50,512) x@W+b (fp32)
__device__ float  g_hs    [Bb * Ss * Dd];     // LSTM outputs (tf32-rounded)
__device__ float  g_qkv   [Bb * Ss * 384];    // fused q|k|v
__device__ float  g_att   [Bb * Ss * Dd];     // attn out, pre-Wo (tf32-rounded)
__device__ float  g_stm   [Bb * Ss * Dd];     // MHA out (post-Wo)
__device__ float  g_qvec  [Bb * Dd];
__device__ float  g_short [Bb * Dd];
__device__ float  g_long  [Bb * Dd];
__device__ __half g_Uh    [G4 * Dd];          // U^T as fp16: [n=512][k=128]
__device__ float  g_Wr    [Dd * G4];          // tf32-rounded lstm_W
__device__ float  g_Wqkv  [Dd * 384];         // tf32-rounded packed Wq|Wk|Wv
__device__ float  g_Wor   [Dd * Dd];          // tf32-rounded Wo
__device__ float  g_W1r   [UE * Dd];          // tf32-rounded W1

__device__ __forceinline__ float sigm(float x) { return 1.0f / (1.0f + __expf(-x)); }
__device__ __forceinline__ float tanh_fast(float x) {
    return 1.0f - 2.0f / (1.0f + __expf(2.0f * x));
}

__device__ __forceinline__ float to_tf32(float x) {
    uint32_t u;
    asm("cvt.rna.tf32.f32 %0, %1;" : "=r"(u) : "f"(x));
    return __uint_as_float(u);
}

__device__ __forceinline__ void cp16(void* smem, const void* g) {
    uint32_t s = (uint32_t)__cvta_generic_to_shared(smem);
    asm volatile("cp.async.ca.shared.global [%0], [%1], 16;" :: "r"(s), "l"(g));
}

__device__ __forceinline__ void mma_tf32(float* c, const uint32_t* a, const uint32_t* b) {
    asm volatile(
        "mma.sync.aligned.m16n8k8.row.col.f32.tf32.tf32.f32 "
        "{%0,%1,%2,%3}, {%4,%5,%6,%7}, {%8,%9}, {%0,%1,%2,%3};"
        : "+f"(c[0]), "+f"(c[1]), "+f"(c[2]), "+f"(c[3])
        : "r"(a[0]), "r"(a[1]), "r"(a[2]), "r"(a[3]), "r"(b[0]), "r"(b[1]));
}

__device__ __forceinline__ void mma_f16(float* c, const uint32_t* a, const uint32_t* b) {
    asm volatile(
        "mma.sync.aligned.m16n8k16.row.col.f32.f16.f16.f32 "
        "{%0,%1,%2,%3}, {%4,%5,%6,%7}, {%8,%9}, {%0,%1,%2,%3};"
        : "+f"(c[0]), "+f"(c[1]), "+f"(c[2]), "+f"(c[3])
        : "r"(a[0]), "r"(a[1]), "r"(a[2]), "r"(a[3]), "r"(b[0]), "r"(b[1]));
}

__device__ __forceinline__ void ldsm_x4(uint32_t& r0, uint32_t& r1, uint32_t& r2,
                                        uint32_t& r3, uint32_t addr) {
    asm volatile("ldmatrix.sync.aligned.m8n8.x4.shared.b16 {%0,%1,%2,%3}, [%4];"
                 : "=r"(r0), "=r"(r1), "=r"(r2), "=r"(r3) : "r"(addr));
}

__device__ __forceinline__ void ldsm_x2(uint32_t& r0, uint32_t& r1, uint32_t addr) {
    asm volatile("ldmatrix.sync.aligned.m8n8.x2.shared.b16 {%0,%1}, [%2];"
                 : "=r"(r0), "=r"(r1) : "r"(addr));
}

// ---------------- 1) embedding gathers --------------------------------------
__global__ void gather_kernel(const int* __restrict__ up, const int* __restrict__ stb,
                              const float* __restrict__ emb) {
    int idx = blockIdx.x * blockDim.x + threadIdx.x;
    const int n1 = Bb * UE;
    if (idx < n1) {
        int b = idx / UE, r = idx % UE;
        int u = r / Ee, e = r % Ee;
        float v = emb[up[b * Uu + u] * Ee + e];
        g_user_e[idx] = v;
        g_user_t[idx] = to_tf32(v);
    }
    int idx2 = idx - n1;
    if (idx2 >= 0 && idx2 < Bb * Ss * Dd) {
        int e = idx2 & (Ee - 1);
        int t = idx2 / Ee;            // (b*S+s)*F + f
        int f = t & (Ff - 1);
        int bs = t / Ff;              // b*S+s
        g_stx[idx2] = to_tf32(emb[stb[bs * Ff + f] * Ee + e]);
    }
}

// ---------------- 2) weight repacks ----------------------------------------
__global__ void repackU_kernel(const float* __restrict__ Uw) {
    int idx = blockIdx.x * blockDim.x + threadIdx.x;   // 65536
    if (idx >= G4 * Dd) return;
    int n = idx >> 7, k = idx & 127;
    g_Uh[idx] = __float2half(Uw[k * G4 + n]);
}

__global__ void repackW_kernel(const float* __restrict__ lstm_W,
                               const float* __restrict__ Wq,
                               const float* __restrict__ Wk,
                               const float* __restrict__ Wv,
                               const float* __restrict__ Wo,
                               const float* __restrict__ W1) {
    int idx = blockIdx.x * blockDim.x + threadIdx.x;
    if (idx < Dd * G4) {
        g_Wr[idx] = to_tf32(lstm_W[idx]);
        return;
    }
    int j = idx - Dd * G4;
    if (j < Dd * 384) {
        int k = j / 384, n = j % 384;
        float v = (n < 128) ? Wq[k * Dd + n]
                : (n < 256) ? Wk[k * Dd + (n - 128)]
                            : Wv[k * Dd + (n - 256)];
        g_Wqkv[j] = to_tf32(v);
        return;
    }
    j -= Dd * 384;
    if (j < Dd * Dd) { g_Wor[j] = to_tf32(Wo[j]); return; }
    j -= Dd * Dd;
    if (j < UE * Dd) g_W1r[j] = to_tf32(W1[j]);
}

// ---------------- tf32 tensor-core GEMM: C[M,N]=A[M,K]@W[K,N] (+bias) -------
__global__ __launch_bounds__(256, 2) void gemm_tf32(
    const float* __restrict__ A, const float* __restrict__ W,
    const float* __restrict__ bias, float* __restrict__ C,
    int M, int N, int K) {
    __shared__ float As[128][36];
    __shared__ float Bs[32][136];
    int tid = threadIdx.x;
    int lane = tid & 31, warp = tid >> 5;
    int wm = warp >> 1, wn = warp & 1;
    int g = lane >> 2, tig = lane & 3;
    int m0 = blockIdx.y * 128, n0 = blockIdx.x * 128;

    float c[2][8][4];
#pragma unroll
    for (int i = 0; i < 2; i++)
#pragma unroll
        for (int j = 0; j < 8; j++)
#pragma unroll
            for (int l = 0; l < 4; l++) c[i][j][l] = 0.f;

    for (int k0 = 0; k0 < K; k0 += 32) {
        if (k0) __syncthreads();
#pragma unroll
        for (int i = 0; i < 4; i++) {
            int idx = tid + i * 256;
            int r = idx >> 3, c4 = (idx & 7) * 4;
            cp16(&As[r][c4], &A[(m0 + r) * K + k0 + c4]);
        }
#pragma unroll
        for (int i = 0; i < 4; i++) {
            int idx = tid + i * 256;
            int r = idx >> 5, c4 = (idx & 31) * 4;
            cp16(&Bs[r][c4], &W[(k0 + r) * N + n0 + c4]);
        }
        asm volatile("cp.async.commit_group;");
        asm volatile("cp.async.wait_group 0;");
        __syncthreads();

#pragma unroll
        for (int kk = 0; kk < 32; kk += 8) {
            uint32_t a[2][4], b[8][2];
#pragma unroll
            for (int mt = 0; mt < 2; mt++) {
                int mr = wm * 32 + mt * 16;
                a[mt][0] = __float_as_uint(As[mr + g][kk + tig]);
                a[mt][1] = __float_as_uint(As[mr + g + 8][kk + tig]);
                a[mt][2] = __float_as_uint(As[mr + g][kk + tig + 4]);
                a[mt][3] = __float_as_uint(As[mr + g + 8][kk + tig + 4]);
            }
#pragma unroll
            for (int nt = 0; nt < 8; nt++) {
                int nc = wn * 64 + nt * 8 + g;
                b[nt][0] = __float_as_uint(Bs[kk + tig][nc]);
                b[nt][1] = __float_as_uint(Bs[kk + tig + 4][nc]);
            }
#pragma unroll
            for (int mt = 0; mt < 2; mt++)
#pragma unroll
                for (int nt = 0; nt < 8; nt++)
                    mma_tf32(c[mt][nt], a[mt], b[nt]);
        }
    }

#pragma unroll
    for (int mt = 0; mt < 2; mt++) {
        int row = m0 + wm * 32 + mt * 16 + g;
#pragma unroll
        for (int nt = 0; nt < 8; nt++) {
            int col = n0 + wn * 64 + nt * 8 + 2 * tig;
            float bx = 0.f, by = 0.f;
            if (bias) { bx = bias[col]; by = bias[col + 1]; }
            float2 o0 = make_float2(c[mt][nt][0] + bx, c[mt][nt][1] + by);
            float2 o1 = make_float2(c[mt][nt][2] + bx, c[mt][nt][3] + by);
            *(float2*)&C[row * N + col] = o0;
            *(float2*)&C[(row + 8) * N + col] = o1;
        }
    }
}

// ---------------- 3) LSTM: fp16 mma, reg-resident U, 8 rows/CTA -------------
// 128 CTAs x 8 batch rows, 512 threads (16 warps). Warp w owns n-slice
// [w*32, w*32+32). U fragments (64 regs/thread) ldsm'd ONCE before the step
// loop. Per step per warp: 8x ldsm_x4 (A) + 32 mma. A rows 8-15 are zero
// (m16 tile, 8 live rows). Epilogue: thread (erow=tid>>6, d0=(tid&63)*2)
// owns 2 cells; exp-based sigmoid/tanh; h written fp16 (hbuf) + tf32 (g_hs).
#define UT_STRIDE 136          // fp16 elems per Ut row (conflict-free ldmatrix)
#define HB_STRIDE 136
#define ZB_STRIDE 520
#define LSTM_ROWS 8
#define LSTM_SMEM_BYTES (G4 * UT_STRIDE * 2 + 16 * HB_STRIDE * 2 + LSTM_ROWS * ZB_STRIDE * 4)

__global__ __launch_bounds__(512, 1) void lstm_mma_kernel(
    const float* __restrict__ xW, float* __restrict__ hs) {
    extern __shared__ __align__(16) char smem_raw[];
    __half* Ut   = (__half*)smem_raw;                                   // [512][136]
    __half* hbuf = (__half*)(smem_raw + G4 * UT_STRIDE * 2);            // [16][136]
    float*  zbuf = (float*)(smem_raw + G4 * UT_STRIDE * 2 + 16 * HB_STRIDE * 2); // [8][520]

    int tid = threadIdx.x;
    int lane = tid & 31, warp = tid >> 5;
    int b0 = blockIdx.x * LSTM_ROWS;

    // ---- stage U^T into smem (cp.async), zero hbuf (16 rows; 8-15 stay 0) --
    for (int i = tid; i < G4 * Dd / 8; i += 512) {     // 8192 16B chunks
        int n = i >> 4, c = (i & 15) * 8;
        cp16(&Ut[n * UT_STRIDE + c], &g_Uh[n * Dd + c]);
    }
    for (int i = tid; i < 16 * HB_STRIDE; i += 512) hbuf[i] = __float2half(0.f);
    asm volatile("cp.async.commit_group;");
    asm volatile("cp.async.wait_group 0;");
    __syncthreads();

    // ---- per-lane ldmatrix base addresses ----
    uint32_t hb_base = (uint32_t)__cvta_generic_to_shared(hbuf);
    uint32_t ut_base = (uint32_t)__cvta_generic_to_shared(Ut);
    int arow = lane & 15;
    int akofs = (lane >> 4) * 8;
    uint32_t aAddr = hb_base + (arow * HB_STRIDE + akofs) * 2;
    int bn = lane & 7;
    int bkofs = ((lane >> 3) & 1) * 8;
    int nw = warp * 32;
    uint32_t bAddr = ut_base + ((nw + bn) * UT_STRIDE + bkofs) * 2;

    // ---- preload ALL U fragments into registers (step-invariant) ----
    uint32_t bf[8][4][2];
#pragma unroll
    for (int kt = 0; kt < 8; kt++)
#pragma unroll
        for (int nt = 0; nt < 4; nt++)
            ldsm_x2(bf[kt][nt][0], bf[kt][nt][1],
                    bAddr + nt * (8 * UT_STRIDE * 2) + kt * 32);

    // epilogue ownership: 8 rows x 64 d-pairs
    int erow = tid >> 6, d0 = (tid & 63) * 2;
    float cc0 = 0.f, cc1 = 0.f;
    int gid = lane >> 2, tig = lane & 3;

    for (int step = 0; step < Ss; step++) {
        // prefetch xW gates for this thread's 2 cells (overlaps mma phase)
        const float* xb = xW + ((b0 + erow) * Ss + step) * G4 + d0;
        float2 xi = *(const float2*)&xb[0];
        float2 xf = *(const float2*)&xb[128];
        float2 xg = *(const float2*)&xb[256];
        float2 xo = *(const float2*)&xb[384];

        // ---- mma phase ----
        float acc[4][4];
#pragma unroll
        for (int nt = 0; nt < 4; nt++)
#pragma unroll
            for (int j = 0; j < 4; j++) acc[nt][j] = 0.f;
#pragma unroll
        for (int kt = 0; kt < 8; kt++) {
            uint32_t a[4];
            ldsm_x4(a[0], a[1], a[2], a[3], aAddr + kt * 32);
#pragma unroll
            for (int nt = 0; nt < 4; nt++)
                mma_f16(acc[nt], a, bf[kt][nt]);
        }
        // dump live z fragments (rows 0-7 = c0,c1 of row gid)
#pragma unroll
        for (int nt = 0; nt < 4; nt++) {
            int col = nw + nt * 8 + 2 * tig;
            *(float2*)&zbuf[gid * ZB_STRIDE + col] = make_float2(acc[nt][0], acc[nt][1]);
        }
        __syncthreads();

        // ---- epilogue: 2 cells ----
        float2 zi = *(float2*)&zbuf[erow * ZB_STRIDE + d0];
        float2 zf = *(float2*)&zbuf[erow * ZB_STRIDE + 128 + d0];
        float2 zg = *(float2*)&zbuf[erow * ZB_STRIDE + 256 + d0];
        float2 zo = *(float2*)&zbuf[erow * ZB_STRIDE + 384 + d0];
        float i0 = sigm(zi.x + xi.x), i1 = sigm(zi.y + xi.y);
        float f0 = sigm(zf.x + xf.x), f1 = sigm(zf.y + xf.y);
        float g0 = tanh_fast(zg.x + xg.x), g1 = tanh_fast(zg.y + xg.y);
        float o0 = sigm(zo.x + xo.x), o1 = sigm(zo.y + xo.y);
        cc0 = f0 * cc0 + i0 * g0;
        cc1 = f1 * cc1 + i1 * g1;
        float h0 = o0 * tanh_fast(cc0);
        float h1 = o1 * tanh_fast(cc1);
        *(__half2*)&hbuf[erow * HB_STRIDE + d0] = __floats2half2_rn(h0, h1);
        *(float2*)&hs[((b0 + erow) * Ss + step) * Dd + d0] =
            make_float2(to_tf32(h0), to_tf32(h1));
        __syncthreads();
    }
}

// ---------------- 4) MHA core: one block per (b, head) ----------------------
__global__ __launch_bounds__(128) void mha_kernel() {
    int bh = blockIdx.x;
    int b = bh >> 2, h = bh & 3;
    __shared__ float qs[Ss][Ee], ks[Ss][Ee], vs[Ss][Ee];
    __shared__ float sc[Ss][52];
    int t = threadIdx.x;
    for (int idx = t; idx < Ss * Ee; idx += 128) {
        int s = idx >> 5, e = idx & 31;
        int base = (b * Ss + s) * 384 + h * Ee + e;
        qs[s][e] = g_qkv[base];
        ks[s][e] = g_qkv[base + 128];
        vs[s][e] = g_qkv[base + 256];
    }
    __syncthreads();
    const float scale = 0.17677669529663687f;  // 1/sqrt(32)
    for (int idx = t; idx < Ss * Ss; idx += 128) {
        int r = idx / Ss, c = idx % Ss;
        float a = 0.f;
#pragma unroll
        for (int e = 0; e < Ee; e++) a += qs[r][e] * ks[c][e];
        sc[r][c] = a * scale;
    }
    __syncthreads();
    if (t < Ss) {
        float mx = -3.4e38f;
        for (int c = 0; c < Ss; c++) mx = fmaxf(mx, sc[t][c]);
        float sm = 0.f;
        for (int c = 0; c < Ss; c++) { float e = __expf(sc[t][c] - mx); sc[t][c] = e; sm += e; }
        float inv = 1.f / sm;
        for (int c = 0; c < Ss; c++) sc[t][c] *= inv;
    }
    __syncthreads();
    for (int idx = t; idx < Ss * Ee; idx += 128) {
        int s = idx >> 5, e = idx & 31;
        float a = 0.f;
        for (int c = 0; c < Ss; c++) a += sc[s][c] * vs[c][e];
        g_att[(b * Ss + s) * Dd + h * Ee + e] = to_tf32(a);
    }
}

// ---------------- 5) short-term attention pooling ---------------------------
__global__ __launch_bounds__(128) void shortpool_kernel() {
    int b = blockIdx.x;
    __shared__ float qv[Dd];
    __shared__ float sc[Ss];
    int t = threadIdx.x;
    qv[t] = g_qvec[b * Dd + t];
    __syncthreads();
    if (t < Ss) {
        const float* row = &g_stm[(b * Ss + t) * Dd];
        float a = 0.f;
        for (int k = 0; k < Dd; k++) a += row[k] * qv[k];
        sc[t] = a;
    }
    __syncthreads();
    if (t == 0) {
        float mx = -3.4e38f;
        for (int s = 0; s < Ss; s++) mx = fmaxf(mx, sc[s]);
        float sm = 0.f;
        for (int s = 0; s < Ss; s++) { float e = __expf(sc[s] - mx); sc[s] = e; sm += e; }
        float inv = 1.f / sm;
        for (int s = 0; s < Ss; s++) sc[s] *= inv;
    }
    __syncthreads();
    float a = 0.f;
    for (int s = 0; s < Ss; s++) a += sc[s] * g_stm[(b * Ss + s) * Dd + t];
    g_short[b * Dd + t] = a;
}

// ---------------- 6) long-term field attention (dedup mask) -----------------
__global__ __launch_bounds__(256) void longterm_kernel(const int* __restrict__ ltb,
                                                       const float* __restrict__ emb,
                                                       const float* __restrict__ Wt,
                                                       const float* __restrict__ bt) {
    int bi = blockIdx.x;
    int b = bi >> 2, fi = bi & 3;
    __shared__ int   ids[Ll];
    __shared__ float vecs[Ll][Ee];
    __shared__ float sc[Ll];
    __shared__ float uv[Ee];
    __shared__ float part[8][Ee];
    __shared__ float red[256];
    int t = threadIdx.x;
    if (t < Ll) ids[t] = ltb[(b * Ll + t) * Ff + fi];
    __syncthreads();
    for (int idx = t; idx < Ll * Ee; idx += 256) {
        int l = idx >> 5, e = idx & 31;
        vecs[l][e] = emb[ids[l] * Ee + e];
    }
    {
        int e = t & 31, g = t >> 5;
        float a = 0.f;
        for (int k = g * 32; k < g * 32 + 32; k++)
            a += g_user_e[b * UE + k] * Wt[(fi * UE + k) * Ee + e];
        part[g][e] = a;
    }
    __syncthreads();
    if (t < Ee) {
        float a = bt[fi * Ee + t];
        for (int g = 0; g < 8; g++) a += part[g][t];
        uv[t] = a;
    }
    __syncthreads();
    if (t < Ll) {
        int mid = ids[t];
        bool keep = true;
        for (int j = 0; j < t; j++) if (ids[j] == mid) { keep = false; break; }
        float a = 0.f;
#pragma unroll
        for (int e = 0; e < Ee; e++) a += vecs[t][e] * uv[e];
        sc[t] = keep ? a : NEGV;
    }
    __syncthreads();
    red[t] = (t < Ll) ? sc[t] : -3.4e38f;
    __syncthreads();
    for (int ofs = 128; ofs >= 1; ofs >>= 1) {
        if (t < ofs) red[t] = fmaxf(red[t], red[t + ofs]);
        __syncthreads();
    }
    float mx = red[0];
    __syncthreads();
    float ev = (t < Ll) ? __expf(sc[t] - mx) : 0.f;
    if (t < Ll) sc[t] = ev;
    red[t] = ev;
    __syncthreads();
    for (int ofs = 128; ofs >= 1; ofs >>= 1) {
        if (t < ofs) red[t] += red[t + ofs];
        __syncthreads();
    }
    float inv = 1.f / red[0];
    __syncthreads();
    {
        int e = t & 31, g = t >> 5;
        float a = 0.f;
        for (int l = g; l < Ll; l += 8) a += sc[l] * vecs[l][e];
        part[g][e] = a;
    }
    __syncthreads();
    if (t < Ee) {
        float a = 0.f;
        for (int g = 0; g < 8; g++) a += part[g][t];
        g_long[b * Dd + fi * Ee + t] = a * inv;
    }
}

// ---------------- 7) final gate + mix ---------------------------------------
__global__ __launch_bounds__(128) void gate_kernel(
    const float* __restrict__ Wu, const float* __restrict__ bu,
    const float* __restrict__ Wsg, const float* __restrict__ bsg,
    const float* __restrict__ Wl, const float* __restrict__ bl,
    float* __restrict__ out) {
    int b = blockIdx.x, d = threadIdx.x;
    __shared__ float ue[UE], sh[Dd], lg[Dd];
    ue[d] = g_user_e[b * UE + d];
    ue[d + 128] = g_user_e[b * UE + 128 + d];
    sh[d] = g_short[b * Dd + d];
    lg[d] = g_long[b * Dd + d];
    __syncthreads();
    float a = bu[d] + bsg[d] + bl[d];
    for (int k = 0; k < UE; k++) a += ue[k] * Wu[k * Dd + d];
    for (int k = 0; k < Dd; k++) a += sh[k] * Wsg[k * Dd + d] + lg[k] * Wl[k * Dd + d];
    float g = sigm(a);
    out[b * Dd + d] = (1.f - g) * lg[d] + g * sh[d];
}

// ---------------- host ------------------------------------------------------
static float* sym(const void* s) {
    void* p = nullptr;
    cudaGetSymbolAddress(&p, s);
    return (float*)p;
}

extern "C" void kernel_launch(void* const* d_in, const int* in_sizes, int n_in,
                              void* d_out, int out_size) {
    const int*   up     = (const int*)d_in[0];
    const int*   stb    = (const int*)d_in[1];
    const int*   ltb    = (const int*)d_in[2];
    const float* emb    = (const float*)d_in[3];
    const float* lstm_W = (const float*)d_in[4];
    const float* lstm_U = (const float*)d_in[5];
    const float* lstm_b = (const float*)d_in[6];
    const float* Wq     = (const float*)d_in[7];
    const float* Wk     = (const float*)d_in[8];
    const float* Wv     = (const float*)d_in[9];
    const float* Wo     = (const float*)d_in[10];
    const float* W1     = (const float*)d_in[11];
    const float* b1     = (const float*)d_in[12];
    const float* Wt     = (const float*)d_in[13];
    const float* bt     = (const float*)d_in[14];
    const float* Wu     = (const float*)d_in[15];
    const float* bu     = (const float*)d_in[16];
    const float* Wsg    = (const float*)d_in[17];
    const float* bsg    = (const float*)d_in[18];
    const float* Wl     = (const float*)d_in[19];
    const float* bl     = (const float*)d_in[20];
    float* out = (float*)d_out;

    float* p_user  = sym(g_user_e);
    float* p_usert = sym(g_user_t);
    float* p_stx   = sym(g_stx);
    float* p_xW    = sym(g_xW);
    float* p_hs    = sym(g_hs);
    float* p_qkv   = sym(g_qkv);
    float* p_att   = sym(g_att);
    float* p_stm   = sym(g_stm);
    float* p_qvec  = sym(g_qvec);
    float* p_Wr    = sym(g_Wr);
    float* p_Wqkv  = sym(g_Wqkv);
    float* p_Wor   = sym(g_Wor);
    float* p_W1r   = sym(g_W1r);

    const int MBS = Bb * Ss;  // 51200

    // idempotent, every call (no static guards)
    cudaFuncSetAttribute(lstm_mma_kernel,
                         cudaFuncAttributeMaxDynamicSharedMemorySize,
                         LSTM_SMEM_BYTES);

    // 1) gathers + weight repacks
    {
        int total = Bb * UE + Bb * Ss * Dd;
        gather_kernel<<<(total + 255) / 256, 256>>>(up, stb, emb);
        repackU_kernel<<<(G4 * Dd + 255) / 256, 256>>>(lstm_U);
        int wtotal = Dd * G4 + Dd * 384 + Dd * Dd + UE * Dd;
        repackW_kernel<<<(wtotal + 255) / 256, 256>>>(lstm_W, Wq, Wk, Wv, Wo, W1);
    }
    // 2) xW = stx @ lstm_W + b   (51200 x 512 x 128) tf32
    gemm_tf32<<<dim3(G4 / 128, MBS / 128), 256>>>(p_stx, p_Wr, lstm_b, p_xW, MBS, G4, Dd);
    // 3) LSTM recurrence: fp16 mma, reg-resident U, 128 CTAs x 8 rows
    lstm_mma_kernel<<<Bb / LSTM_ROWS, 512, LSTM_SMEM_BYTES>>>(p_xW, p_hs);
    // 4) fused QKV projection (51200 x 384 x 128) tf32
    gemm_tf32<<<dim3(384 / 128, MBS / 128), 256>>>(p_hs, p_Wqkv, nullptr, p_qkv, MBS, 384, Dd);
    // 5) attention core + output projection
    mha_kernel<<<Bb * Ff, 128>>>();
    gemm_tf32<<<dim3(Dd / 128, MBS / 128), 256>>>(p_att, p_Wor, nullptr, p_stm, MBS, Dd, Dd);
    // 6) pooling query (tf32) + short-term pooling
    gemm_tf32<<<dim3(Dd / 128, Bb / 128), 256>>>(p_usert, p_W1r, b1, p_qvec, Bb, Dd, UE);
    shortpool_kernel<<<Bb, 128>>>();
    // 7) long-term field attention
    longterm_kernel<<<Bb * Ff, 256>>>(ltb, emb, Wt, bt);
    // 8) gate + mix -> out
    gate_kernel<<<Bb, 128>>>(Wu, bu, Wsg, bsg, Wl, bl, out);
}

// round 9
// speedup vs baseline: 1.0763x; 1.0349x over previous
#include <cuda_runtime.h>
#include <cuda_fp16.h>
#include <math.h>
#include <stdint.h>

// Problem constants
#define Bb   1024
#define Uu   8
#define Ss   50
#define Ll   200
#define Ff   4
#define Ee   32
#define Dd   128      // F*E
#define UE   256      // U*E
#define G4   512      // 4*D
#define NEGV -1000000000.0f

// ---------------- scratch (static device globals) ---------------------------
__device__ float  g_user_e[Bb * UE];          // (B,256)
__device__ float  g_user_t[Bb * UE];          // tf32-rounded copy
__device__ float  g_stx   [Bb * Ss * Dd];     // (B,50,128) tf32-rounded
__device__ float  g_xW    [Bb * Ss * G4];     // (B,50,512) x@W+b (fp32)
__device__ float  g_hs    [Bb * Ss * Dd];     // LSTM outputs (tf32-rounded)
__device__ float  g_qkv   [Bb * Ss * 384];    // fused q|k|v
__device__ float  g_att   [Bb * Ss * Dd];     // attn out, pre-Wo (tf32-rounded)
__device__ float  g_stm   [Bb * Ss * Dd];     // MHA out (post-Wo)
__device__ float  g_qvec  [Bb * Dd];
__device__ float  g_short [Bb * Dd];
__device__ float  g_long  [Bb * Dd];
__device__ __half g_Uh    [G4 * Dd];          // U^T as fp16: [n=512][k=128]
__device__ float  g_Wr    [Dd * G4];          // tf32-rounded lstm_W
__device__ float  g_Wqkv  [Dd * 384];         // tf32-rounded packed Wq|Wk|Wv
__device__ float  g_Wor   [Dd * Dd];          // tf32-rounded Wo
__device__ float  g_W1r   [UE * Dd];          // tf32-rounded W1

__device__ __forceinline__ float sigm(float x) { return 1.0f / (1.0f + __expf(-x)); }

__device__ __forceinline__ float tanh_mufu(float x) {
    float y;
    asm("tanh.approx.f32 %0, %1;" : "=f"(y) : "f"(x));
    return y;
}
__device__ __forceinline__ float sigm_mufu(float x) {
    return fmaf(0.5f, tanh_mufu(0.5f * x), 0.5f);
}

__device__ __forceinline__ float to_tf32(float x) {
    uint32_t u;
    asm("cvt.rna.tf32.f32 %0, %1;" : "=r"(u) : "f"(x));
    return __uint_as_float(u);
}

__device__ __forceinline__ void cp16(void* smem, const void* g) {
    uint32_t s = (uint32_t)__cvta_generic_to_shared(smem);
    asm volatile("cp.async.ca.shared.global [%0], [%1], 16;" :: "r"(s), "l"(g));
}

__device__ __forceinline__ void mma_tf32(float* c, const uint32_t* a, const uint32_t* b) {
    asm volatile(
        "mma.sync.aligned.m16n8k8.row.col.f32.tf32.tf32.f32 "
        "{%0,%1,%2,%3}, {%4,%5,%6,%7}, {%8,%9}, {%0,%1,%2,%3};"
        : "+f"(c[0]), "+f"(c[1]), "+f"(c[2]), "+f"(c[3])
        : "r"(a[0]), "r"(a[1]), "r"(a[2]), "r"(a[3]), "r"(b[0]), "r"(b[1]));
}

__device__ __forceinline__ void mma_f16(float* c, const uint32_t* a, const uint32_t* b) {
    asm volatile(
        "mma.sync.aligned.m16n8k16.row.col.f32.f16.f16.f32 "
        "{%0,%1,%2,%3}, {%4,%5,%6,%7}, {%8,%9}, {%0,%1,%2,%3};"
        : "+f"(c[0]), "+f"(c[1]), "+f"(c[2]), "+f"(c[3])
        : "r"(a[0]), "r"(a[1]), "r"(a[2]), "r"(a[3]), "r"(b[0]), "r"(b[1]));
}

__device__ __forceinline__ void ldsm_x4(uint32_t& r0, uint32_t& r1, uint32_t& r2,
                                        uint32_t& r3, uint32_t addr) {
    asm volatile("ldmatrix.sync.aligned.m8n8.x4.shared.b16 {%0,%1,%2,%3}, [%4];"
                 : "=r"(r0), "=r"(r1), "=r"(r2), "=r"(r3) : "r"(addr));
}

__device__ __forceinline__ void ldsm_x2(uint32_t& r0, uint32_t& r1, uint32_t addr) {
    asm volatile("ldmatrix.sync.aligned.m8n8.x2.shared.b16 {%0,%1}, [%2];"
                 : "=r"(r0), "=r"(r1) : "r"(addr));
}

// ---------------- 1) embedding gathers --------------------------------------
__global__ void gather_kernel(const int* __restrict__ up, const int* __restrict__ stb,
                              const float* __restrict__ emb) {
    int idx = blockIdx.x * blockDim.x + threadIdx.x;
    const int n1 = Bb * UE;
    if (idx < n1) {
        int b = idx / UE, r = idx % UE;
        int u = r / Ee, e = r % Ee;
        float v = emb[up[b * Uu + u] * Ee + e];
        g_user_e[idx] = v;
        g_user_t[idx] = to_tf32(v);
    }
    int idx2 = idx - n1;
    if (idx2 >= 0 && idx2 < Bb * Ss * Dd) {
        int e = idx2 & (Ee - 1);
        int t = idx2 / Ee;            // (b*S+s)*F + f
        int f = t & (Ff - 1);
        int bs = t / Ff;              // b*S+s
        g_stx[idx2] = to_tf32(emb[stb[bs * Ff + f] * Ee + e]);
    }
}

// ---------------- 2) weight repacks ----------------------------------------
__global__ void repackU_kernel(const float* __restrict__ Uw) {
    int idx = blockIdx.x * blockDim.x + threadIdx.x;   // 65536
    if (idx >= G4 * Dd) return;
    int n = idx >> 7, k = idx & 127;
    g_Uh[idx] = __float2half(Uw[k * G4 + n]);
}

__global__ void repackW_kernel(const float* __restrict__ lstm_W,
                               const float* __restrict__ Wq,
                               const float* __restrict__ Wk,
                               const float* __restrict__ Wv,
                               const float* __restrict__ Wo,
                               const float* __restrict__ W1) {
    int idx = blockIdx.x * blockDim.x + threadIdx.x;
    if (idx < Dd * G4) {
        g_Wr[idx] = to_tf32(lstm_W[idx]);
        return;
    }
    int j = idx - Dd * G4;
    if (j < Dd * 384) {
        int k = j / 384, n = j % 384;
        float v = (n < 128) ? Wq[k * Dd + n]
                : (n < 256) ? Wk[k * Dd + (n - 128)]
                            : Wv[k * Dd + (n - 256)];
        g_Wqkv[j] = to_tf32(v);
        return;
    }
    j -= Dd * 384;
    if (j < Dd * Dd) { g_Wor[j] = to_tf32(Wo[j]); return; }
    j -= Dd * Dd;
    if (j < UE * Dd) g_W1r[j] = to_tf32(W1[j]);
}

// ---------------- tf32 tensor-core GEMM: C[M,N]=A[M,K]@W[K,N] (+bias) -------
__global__ __launch_bounds__(256, 2) void gemm_tf32(
    const float* __restrict__ A, const float* __restrict__ W,
    const float* __restrict__ bias, float* __restrict__ C,
    int M, int N, int K) {
    __shared__ float As[128][36];
    __shared__ float Bs[32][136];
    int tid = threadIdx.x;
    int lane = tid & 31, warp = tid >> 5;
    int wm = warp >> 1, wn = warp & 1;
    int g = lane >> 2, tig = lane & 3;
    int m0 = blockIdx.y * 128, n0 = blockIdx.x * 128;

    float c[2][8][4];
#pragma unroll
    for (int i = 0; i < 2; i++)
#pragma unroll
        for (int j = 0; j < 8; j++)
#pragma unroll
            for (int l = 0; l < 4; l++) c[i][j][l] = 0.f;

    for (int k0 = 0; k0 < K; k0 += 32) {
        if (k0) __syncthreads();
#pragma unroll
        for (int i = 0; i < 4; i++) {
            int idx = tid + i * 256;
            int r = idx >> 3, c4 = (idx & 7) * 4;
            cp16(&As[r][c4], &A[(m0 + r) * K + k0 + c4]);
        }
#pragma unroll
        for (int i = 0; i < 4; i++) {
            int idx = tid + i * 256;
            int r = idx >> 5, c4 = (idx & 31) * 4;
            cp16(&Bs[r][c4], &W[(k0 + r) * N + n0 + c4]);
        }
        asm volatile("cp.async.commit_group;");
        asm volatile("cp.async.wait_group 0;");
        __syncthreads();

#pragma unroll
        for (int kk = 0; kk < 32; kk += 8) {
            uint32_t a[2][4], b[8][2];
#pragma unroll
            for (int mt = 0; mt < 2; mt++) {
                int mr = wm * 32 + mt * 16;
                a[mt][0] = __float_as_uint(As[mr + g][kk + tig]);
                a[mt][1] = __float_as_uint(As[mr + g + 8][kk + tig]);
                a[mt][2] = __float_as_uint(As[mr + g][kk + tig + 4]);
                a[mt][3] = __float_as_uint(As[mr + g + 8][kk + tig + 4]);
            }
#pragma unroll
            for (int nt = 0; nt < 8; nt++) {
                int nc = wn * 64 + nt * 8 + g;
                b[nt][0] = __float_as_uint(Bs[kk + tig][nc]);
                b[nt][1] = __float_as_uint(Bs[kk + tig + 4][nc]);
            }
#pragma unroll
            for (int mt = 0; mt < 2; mt++)
#pragma unroll
                for (int nt = 0; nt < 8; nt++)
                    mma_tf32(c[mt][nt], a[mt], b[nt]);
        }
    }

#pragma unroll
    for (int mt = 0; mt < 2; mt++) {
        int row = m0 + wm * 32 + mt * 16 + g;
#pragma unroll
        for (int nt = 0; nt < 8; nt++) {
            int col = n0 + wn * 64 + nt * 8 + 2 * tig;
            float bx = 0.f, by = 0.f;
            if (bias) { bx = bias[col]; by = bias[col + 1]; }
            float2 o0 = make_float2(c[mt][nt][0] + bx, c[mt][nt][1] + by);
            float2 o1 = make_float2(c[mt][nt][2] + bx, c[mt][nt][3] + by);
            *(float2*)&C[row * N + col] = o0;
            *(float2*)&C[(row + 8) * N + col] = o1;
        }
    }
}

// ---------------- 3) LSTM: fp16 mma, gate-aligned frags, 1 sync/step --------
// 128 CTAs x 8 rows, 256 threads (8 warps). Warp w owns d-cols [w*16,w*16+16)
// across ALL 4 gates: B n-rows = gate*128 + w*16 + t*8 (t=0,1). U fragments
// (128 regs) are truly register-resident at the 255-reg budget. Each lane's
// accumulators are exactly the 4 gate pre-activations of its own 4 cells
// (row gid, cols w*16+{2tig,2tig+1,8+2tig,8+2tig+1}) -> in-register epilogue,
// no zbuf. h double-buffered (p/p^1) -> ONE __syncthreads per step.
#define UT_STRIDE 136          // fp16 elems per Ut row (conflict-free ldmatrix)
#define HB_STRIDE 136
#define LSTM_ROWS 8
#define LSTM_SMEM_BYTES (G4 * UT_STRIDE * 2 + 2 * 16 * HB_STRIDE * 2)

__global__ __launch_bounds__(256, 1) void lstm_mma_kernel(
    const float* __restrict__ xW, float* __restrict__ hs) {
    extern __shared__ __align__(16) char smem_raw[];
    __half* Ut  = (__half*)smem_raw;                          // [512][136]
    __half* hb0 = (__half*)(smem_raw + G4 * UT_STRIDE * 2);   // [16][136]
    __half* hb1 = hb0 + 16 * HB_STRIDE;                       // [16][136]

    int tid = threadIdx.x;
    int lane = tid & 31, warp = tid >> 5;
    int b0 = blockIdx.x * LSTM_ROWS;

    // ---- stage U^T into smem; zero BOTH h buffers (rows 8-15 stay 0) ----
    for (int i = tid; i < G4 * Dd / 8; i += 256) {            // 8192 16B chunks
        int n = i >> 4, c = (i & 15) * 8;
        cp16(&Ut[n * UT_STRIDE + c], &g_Uh[n * Dd + c]);
    }
    for (int i = tid; i < 2 * 16 * HB_STRIDE; i += 256) hb0[i] = __float2half(0.f);
    asm volatile("cp.async.commit_group;");
    asm volatile("cp.async.wait_group 0;");
    __syncthreads();

    // ---- ldmatrix A base addresses (both buffers) ----
    int arow = lane & 15;
    int akofs = (lane >> 4) * 8;
    uint32_t aAddr0 = (uint32_t)__cvta_generic_to_shared(hb0) +
                      (arow * HB_STRIDE + akofs) * 2;
    uint32_t aAddr1 = (uint32_t)__cvta_generic_to_shared(hb1) +
                      (arow * HB_STRIDE + akofs) * 2;

    // ---- preload ALL U fragments (gate-aligned), step-invariant ----
    uint32_t ut_base = (uint32_t)__cvta_generic_to_shared(Ut);
    int bn = lane & 7;
    int bkofs = ((lane >> 3) & 1) * 8;
    uint32_t bf[8][4][2][2];                                  // [kt][gate][tile][2]
#pragma unroll
    for (int g = 0; g < 4; g++)
#pragma unroll
        for (int t = 0; t < 2; t++) {
            uint32_t base = ut_base +
                ((g * 128 + warp * 16 + t * 8 + bn) * UT_STRIDE + bkofs) * 2;
#pragma unroll
            for (int kt = 0; kt < 8; kt++)
                ldsm_x2(bf[kt][g][t][0], bf[kt][g][t][1], base + kt * 32);
        }

    int gid = lane >> 2, tig = lane & 3;
    int colt0 = warp * 16 + 2 * tig;      // tile 0 col pair
    int colt1 = colt0 + 8;                // tile 1 col pair
    float cc[2][2] = {{0.f, 0.f}, {0.f, 0.f}};

    int p = 0;
    for (int step = 0; step < Ss; step++) {
        // prefetch xW: 4 gates x 2 tiles x float2 (this lane's cells)
        const float* xb = xW + ((b0 + gid) * Ss + step) * G4;
        float2 xg_[4][2];
#pragma unroll
        for (int g = 0; g < 4; g++) {
            xg_[g][0] = *(const float2*)&xb[g * 128 + colt0];
            xg_[g][1] = *(const float2*)&xb[g * 128 + colt1];
        }

        // ---- mma phase: z = h @ U for this warp's 16 cols x 4 gates ----
        float acc[4][2][4];
#pragma unroll
        for (int g = 0; g < 4; g++)
#pragma unroll
            for (int t = 0; t < 2; t++)
#pragma unroll
                for (int j = 0; j < 4; j++) acc[g][t][j] = 0.f;
        uint32_t aAddr = p ? aAddr1 : aAddr0;
#pragma unroll
        for (int kt = 0; kt < 8; kt++) {
            uint32_t a[4];
            ldsm_x4(a[0], a[1], a[2], a[3], aAddr + kt * 32);
#pragma unroll
            for (int g = 0; g < 4; g++)
#pragma unroll
                for (int t = 0; t < 2; t++)
                    mma_f16(acc[g][t], a, bf[kt][g][t]);
        }

        // ---- in-register epilogue: 4 cells (rows gid; c0/c1 = rows 0-7) ----
        float h_[2][2];
#pragma unroll
        for (int t = 0; t < 2; t++)
#pragma unroll
            for (int u = 0; u < 2; u++) {
                float xi = u ? xg_[0][t].y : xg_[0][t].x;
                float xf = u ? xg_[1][t].y : xg_[1][t].x;
                float xg = u ? xg_[2][t].y : xg_[2][t].x;
                float xo = u ? xg_[3][t].y : xg_[3][t].x;
                float iv = sigm_mufu(acc[0][t][u] + xi);
                float fv = sigm_mufu(acc[1][t][u] + xf);
                float gv = tanh_mufu(acc[2][t][u] + xg);
                float ov = sigm_mufu(acc[3][t][u] + xo);
                cc[t][u] = fv * cc[t][u] + iv * gv;
                h_[t][u] = ov * tanh_mufu(cc[t][u]);
            }

        // write h to the OTHER buffer (no WAR with concurrent ldsm readers)
        __half* hw = p ? hb0 : hb1;
        *(__half2*)&hw[gid * HB_STRIDE + colt0] = __floats2half2_rn(h_[0][0], h_[0][1]);
        *(__half2*)&hw[gid * HB_STRIDE + colt1] = __floats2half2_rn(h_[1][0], h_[1][1]);
        float* hsrow = &hs[((b0 + gid) * Ss + step) * Dd];
        *(float2*)&hsrow[colt0] = make_float2(to_tf32(h_[0][0]), to_tf32(h_[0][1]));
        *(float2*)&hsrow[colt1] = make_float2(to_tf32(h_[1][0]), to_tf32(h_[1][1]));
        __syncthreads();
        p ^= 1;
    }
}

// ---------------- 4) MHA core: one block per (b, head) ----------------------
__global__ __launch_bounds__(128) void mha_kernel() {
    int bh = blockIdx.x;
    int b = bh >> 2, h = bh & 3;
    __shared__ float qs[Ss][Ee], ks[Ss][Ee], vs[Ss][Ee];
    __shared__ float sc[Ss][52];
    int t = threadIdx.x;
    for (int idx = t; idx < Ss * Ee; idx += 128) {
        int s = idx >> 5, e = idx & 31;
        int base = (b * Ss + s) * 384 + h * Ee + e;
        qs[s][e] = g_qkv[base];
        ks[s][e] = g_qkv[base + 128];
        vs[s][e] = g_qkv[base + 256];
    }
    __syncthreads();
    const float scale = 0.17677669529663687f;  // 1/sqrt(32)
    for (int idx = t; idx < Ss * Ss; idx += 128) {
        int r = idx / Ss, c = idx % Ss;
        float a = 0.f;
#pragma unroll
        for (int e = 0; e < Ee; e++) a += qs[r][e] * ks[c][e];
        sc[r][c] = a * scale;
    }
    __syncthreads();
    if (t < Ss) {
        float mx = -3.4e38f;
        for (int c = 0; c < Ss; c++) mx = fmaxf(mx, sc[t][c]);
        float sm = 0.f;
        for (int c = 0; c < Ss; c++) { float e = __expf(sc[t][c] - mx); sc[t][c] = e; sm += e; }
        float inv = 1.f / sm;
        for (int c = 0; c < Ss; c++) sc[t][c] *= inv;
    }
    __syncthreads();
    for (int idx = t; idx < Ss * Ee; idx += 128) {
        int s = idx >> 5, e = idx & 31;
        float a = 0.f;
        for (int c = 0; c < Ss; c++) a += sc[s][c] * vs[c][e];
        g_att[(b * Ss + s) * Dd + h * Ee + e] = to_tf32(a);
    }
}

// ---------------- 5) short-term attention pooling ---------------------------
__global__ __launch_bounds__(128) void shortpool_kernel() {
    int b = blockIdx.x;
    __shared__ float qv[Dd];
    __shared__ float sc[Ss];
    int t = threadIdx.x;
    qv[t] = g_qvec[b * Dd + t];
    __syncthreads();
    if (t < Ss) {
        const float* row = &g_stm[(b * Ss + t) * Dd];
        float a = 0.f;
        for (int k = 0; k < Dd; k++) a += row[k] * qv[k];
        sc[t] = a;
    }
    __syncthreads();
    if (t == 0) {
        float mx = -3.4e38f;
        for (int s = 0; s < Ss; s++) mx = fmaxf(mx, sc[s]);
        float sm = 0.f;
        for (int s = 0; s < Ss; s++) { float e = __expf(sc[s] - mx); sc[s] = e; sm += e; }
        float inv = 1.f / sm;
        for (int s = 0; s < Ss; s++) sc[s] *= inv;
    }
    __syncthreads();
    float a = 0.f;
    for (int s = 0; s < Ss; s++) a += sc[s] * g_stm[(b * Ss + s) * Dd + t];
    g_short[b * Dd + t] = a;
}

// ---------------- 6) long-term field attention (dedup mask) -----------------
__global__ __launch_bounds__(256) void longterm_kernel(const int* __restrict__ ltb,
                                                       const float* __restrict__ emb,
                                                       const float* __restrict__ Wt,
                                                       const float* __restrict__ bt) {
    int bi = blockIdx.x;
    int b = bi >> 2, fi = bi & 3;
    __shared__ int   ids[Ll];
    __shared__ float vecs[Ll][Ee];
    __shared__ float sc[Ll];
    __shared__ float uv[Ee];
    __shared__ float part[8][Ee];
    __shared__ float red[256];
    int t = threadIdx.x;
    if (t < Ll) ids[t] = ltb[(b * Ll + t) * Ff + fi];
    __syncthreads();
    for (int idx = t; idx < Ll * Ee; idx += 256) {
        int l = idx >> 5, e = idx & 31;
        vecs[l][e] = emb[ids[l] * Ee + e];
    }
    {
        int e = t & 31, g = t >> 5;
        float a = 0.f;
        for (int k = g * 32; k < g * 32 + 32; k++)
            a += g_user_e[b * UE + k] * Wt[(fi * UE + k) * Ee + e];
        part[g][e] = a;
    }
    __syncthreads();
    if (t < Ee) {
        float a = bt[fi * Ee + t];
        for (int g = 0; g < 8; g++) a += part[g][t];
        uv[t] = a;
    }
    __syncthreads();
    if (t < Ll) {
        int mid = ids[t];
        bool keep = true;
        for (int j = 0; j < t; j++) if (ids[j] == mid) { keep = false; break; }
        float a = 0.f;
#pragma unroll
        for (int e = 0; e < Ee; e++) a += vecs[t][e] * uv[e];
        sc[t] = keep ? a : NEGV;
    }
    __syncthreads();
    red[t] = (t < Ll) ? sc[t] : -3.4e38f;
    __syncthreads();
    for (int ofs = 128; ofs >= 1; ofs >>= 1) {
        if (t < ofs) red[t] = fmaxf(red[t], red[t + ofs]);
        __syncthreads();
    }
    float mx = red[0];
    __syncthreads();
    float ev = (t < Ll) ? __expf(sc[t] - mx) : 0.f;
    if (t < Ll) sc[t] = ev;
    red[t] = ev;
    __syncthreads();
    for (int ofs = 128; ofs >= 1; ofs >>= 1) {
        if (t < ofs) red[t] += red[t + ofs];
        __syncthreads();
    }
    float inv = 1.f / red[0];
    __syncthreads();
    {
        int e = t & 31, g = t >> 5;
        float a = 0.f;
        for (int l = g; l < Ll; l += 8) a += sc[l] * vecs[l][e];
        part[g][e] = a;
    }
    __syncthreads();
    if (t < Ee) {
        float a = 0.f;
        for (int g = 0; g < 8; g++) a += part[g][t];
        g_long[b * Dd + fi * Ee + t] = a * inv;
    }
}

// ---------------- 7) final gate + mix ---------------------------------------
__global__ __launch_bounds__(128) void gate_kernel(
    const float* __restrict__ Wu, const float* __restrict__ bu,
    const float* __restrict__ Wsg, const float* __restrict__ bsg,
    const float* __restrict__ Wl, const float* __restrict__ bl,
    float* __restrict__ out) {
    int b = blockIdx.x, d = threadIdx.x;
    __shared__ float ue[UE], sh[Dd], lg[Dd];
    ue[d] = g_user_e[b * UE + d];
    ue[d + 128] = g_user_e[b * UE + 128 + d];
    sh[d] = g_short[b * Dd + d];
    lg[d] = g_long[b * Dd + d];
    __syncthreads();
    float a = bu[d] + bsg[d] + bl[d];
    for (int k = 0; k < UE; k++) a += ue[k] * Wu[k * Dd + d];
    for (int k = 0; k < Dd; k++) a += sh[k] * Wsg[k * Dd + d] + lg[k] * Wl[k * Dd + d];
    float g = sigm(a);
    out[b * Dd + d] = (1.f - g) * lg[d] + g * sh[d];
}

// ---------------- host ------------------------------------------------------
static float* sym(const void* s) {
    void* p = nullptr;
    cudaGetSymbolAddress(&p, s);
    return (float*)p;
}

extern "C" void kernel_launch(void* const* d_in, const int* in_sizes, int n_in,
                              void* d_out, int out_size) {
    const int*   up     = (const int*)d_in[0];
    const int*   stb    = (const int*)d_in[1];
    const int*   ltb    = (const int*)d_in[2];
    const float* emb    = (const float*)d_in[3];
    const float* lstm_W = (const float*)d_in[4];
    const float* lstm_U = (const float*)d_in[5];
    const float* lstm_b = (const float*)d_in[6];
    const float* Wq     = (const float*)d_in[7];
    const float* Wk     = (const float*)d_in[8];
    const float* Wv     = (const float*)d_in[9];
    const float* Wo     = (const float*)d_in[10];
    const float* W1     = (const float*)d_in[11];
    const float* b1     = (const float*)d_in[12];
    const float* Wt     = (const float*)d_in[13];
    const float* bt     = (const float*)d_in[14];
    const float* Wu     = (const float*)d_in[15];
    const float* bu     = (const float*)d_in[16];
    const float* Wsg    = (const float*)d_in[17];
    const float* bsg    = (const float*)d_in[18];
    const float* Wl     = (const float*)d_in[19];
    const float* bl     = (const float*)d_in[20];
    float* out = (float*)d_out;

    float* p_user  = sym(g_user_e);
    float* p_usert = sym(g_user_t);
    float* p_stx   = sym(g_stx);
    float* p_xW    = sym(g_xW);
    float* p_hs    = sym(g_hs);
    float* p_qkv   = sym(g_qkv);
    float* p_att   = sym(g_att);
    float* p_stm   = sym(g_stm);
    float* p_qvec  = sym(g_qvec);
    float* p_Wr    = sym(g_Wr);
    float* p_Wqkv  = sym(g_Wqkv);
    float* p_Wor   = sym(g_Wor);
    float* p_W1r   = sym(g_W1r);

    const int MBS = Bb * Ss;  // 51200

    // idempotent, every call (no static guards)
    cudaFuncSetAttribute(lstm_mma_kernel,
                         cudaFuncAttributeMaxDynamicSharedMemorySize,
                         LSTM_SMEM_BYTES);

    // 1) gathers + weight repacks
    {
        int total = Bb * UE + Bb * Ss * Dd;
        gather_kernel<<<(total + 255) / 256, 256>>>(up, stb, emb);
        repackU_kernel<<<(G4 * Dd + 255) / 256, 256>>>(lstm_U);
        int wtotal = Dd * G4 + Dd * 384 + Dd * Dd + UE * Dd;
        repackW_kernel<<<(wtotal + 255) / 256, 256>>>(lstm_W, Wq, Wk, Wv, Wo, W1);
    }
    // 2) xW = stx @ lstm_W + b   (51200 x 512 x 128) tf32
    gemm_tf32<<<dim3(G4 / 128, MBS / 128), 256>>>(p_stx, p_Wr, lstm_b, p_xW, MBS, G4, Dd);
    // 3) LSTM recurrence: fp16 mma, gate-aligned reg-resident U, 128 CTAs
    lstm_mma_kernel<<<Bb / LSTM_ROWS, 256, LSTM_SMEM_BYTES>>>(p_xW, p_hs);
    // 4) fused QKV projection (51200 x 384 x 128) tf32
    gemm_tf32<<<dim3(384 / 128, MBS / 128), 256>>>(p_hs, p_Wqkv, nullptr, p_qkv, MBS, 384, Dd);
    // 5) attention core + output projection
    mha_kernel<<<Bb * Ff, 128>>>();
    gemm_tf32<<<dim3(Dd / 128, MBS / 128), 256>>>(p_att, p_Wor, nullptr, p_stm, MBS, Dd, Dd);
    // 6) pooling query (tf32) + short-term pooling
    gemm_tf32<<<dim3(Dd / 128, Bb / 128), 256>>>(p_usert, p_W1r, b1, p_qvec, Bb, Dd, UE);
    shortpool_kernel<<<Bb, 128>>>();
    // 7) long-term field attention
    longterm_kernel<<<Bb * Ff, 256>>>(ltb, emb, Wt, bt);
    // 8) gate + mix -> out
    gate_kernel<<<Bb, 128>>>(Wu, bu, Wsg, bsg, Wl, bl, out);
}

// round 10
// speedup vs baseline: 1.0788x; 1.0023x over previous
#include <cuda_runtime.h>
#include <cuda_fp16.h>
#include <math.h>
#include <stdint.h>

// Problem constants
#define Bb   1024
#define Uu   8
#define Ss   50
#define Ll   200
#define Ff   4
#define Ee   32
#define Dd   128      // F*E
#define UE   256      // U*E
#define G4   512      // 4*D
#define NEGV -1000000000.0f

// ---------------- scratch (static device globals) ---------------------------
__device__ float  g_user_e[Bb * UE];          // (B,256)
__device__ float  g_user_t[Bb * UE];          // tf32-rounded copy
__device__ float  g_stx   [Bb * Ss * Dd];     // (B,50,128) tf32-rounded
__device__ float  g_xW    [Bb * Ss * G4];     // (B,50,512) x@W+b (fp32)
__device__ float  g_hs    [Bb * Ss * Dd];     // LSTM outputs (tf32-rounded)
__device__ float  g_qkv   [Bb * Ss * 384];    // fused q|k|v
__device__ float  g_att   [Bb * Ss * Dd];     // attn out, pre-Wo (tf32-rounded)
__device__ float  g_stm   [Bb * Ss * Dd];     // MHA out (post-Wo)
__device__ float  g_qvec  [Bb * Dd];
__device__ float  g_short [Bb * Dd];
__device__ float  g_long  [Bb * Dd];
__device__ __half g_Uh    [G4 * Dd];          // U^T as fp16: [n=512][k=128]
__device__ float  g_Wr    [Dd * G4];          // tf32-rounded lstm_W
__device__ float  g_Wqkv  [Dd * 384];         // tf32-rounded packed Wq|Wk|Wv
__device__ float  g_Wor   [Dd * Dd];          // tf32-rounded Wo
__device__ float  g_W1r   [UE * Dd];          // tf32-rounded W1

__device__ __forceinline__ float sigm(float x) { return 1.0f / (1.0f + __expf(-x)); }

__device__ __forceinline__ float tanh_mufu(float x) {
    float y;
    asm("tanh.approx.f32 %0, %1;" : "=f"(y) : "f"(x));
    return y;
}
__device__ __forceinline__ float sigm_mufu(float x) {
    return fmaf(0.5f, tanh_mufu(0.5f * x), 0.5f);
}

__device__ __forceinline__ float to_tf32(float x) {
    uint32_t u;
    asm("cvt.rna.tf32.f32 %0, %1;" : "=r"(u) : "f"(x));
    return __uint_as_float(u);
}

__device__ __forceinline__ void cp16(void* smem, const void* g) {
    uint32_t s = (uint32_t)__cvta_generic_to_shared(smem);
    asm volatile("cp.async.ca.shared.global [%0], [%1], 16;" :: "r"(s), "l"(g));
}

__device__ __forceinline__ void mma_tf32(float* c, const uint32_t* a, const uint32_t* b) {
    asm volatile(
        "mma.sync.aligned.m16n8k8.row.col.f32.tf32.tf32.f32 "
        "{%0,%1,%2,%3}, {%4,%5,%6,%7}, {%8,%9}, {%0,%1,%2,%3};"
        : "+f"(c[0]), "+f"(c[1]), "+f"(c[2]), "+f"(c[3])
        : "r"(a[0]), "r"(a[1]), "r"(a[2]), "r"(a[3]), "r"(b[0]), "r"(b[1]));
}

__device__ __forceinline__ void mma_f16(float* c, const uint32_t* a, const uint32_t* b) {
    asm volatile(
        "mma.sync.aligned.m16n8k16.row.col.f32.f16.f16.f32 "
        "{%0,%1,%2,%3}, {%4,%5,%6,%7}, {%8,%9}, {%0,%1,%2,%3};"
        : "+f"(c[0]), "+f"(c[1]), "+f"(c[2]), "+f"(c[3])
        : "r"(a[0]), "r"(a[1]), "r"(a[2]), "r"(a[3]), "r"(b[0]), "r"(b[1]));
}

__device__ __forceinline__ void ldsm_x4(uint32_t& r0, uint32_t& r1, uint32_t& r2,
                                        uint32_t& r3, uint32_t addr) {
    asm volatile("ldmatrix.sync.aligned.m8n8.x4.shared.b16 {%0,%1,%2,%3}, [%4];"
                 : "=r"(r0), "=r"(r1), "=r"(r2), "=r"(r3) : "r"(addr));
}

__device__ __forceinline__ void ldsm_x2(uint32_t& r0, uint32_t& r1, uint32_t addr) {
    asm volatile("ldmatrix.sync.aligned.m8n8.x2.shared.b16 {%0,%1}, [%2];"
                 : "=r"(r0), "=r"(r1) : "r"(addr));
}

// ---------------- 1) embedding gathers --------------------------------------
__global__ void gather_kernel(const int* __restrict__ up, const int* __restrict__ stb,
                              const float* __restrict__ emb) {
    int idx = blockIdx.x * blockDim.x + threadIdx.x;
    const int n1 = Bb * UE;
    if (idx < n1) {
        int b = idx / UE, r = idx % UE;
        int u = r / Ee, e = r % Ee;
        float v = emb[up[b * Uu + u] * Ee + e];
        g_user_e[idx] = v;
        g_user_t[idx] = to_tf32(v);
    }
    int idx2 = idx - n1;
    if (idx2 >= 0 && idx2 < Bb * Ss * Dd) {
        int e = idx2 & (Ee - 1);
        int t = idx2 / Ee;            // (b*S+s)*F + f
        int f = t & (Ff - 1);
        int bs = t / Ff;              // b*S+s
        g_stx[idx2] = to_tf32(emb[stb[bs * Ff + f] * Ee + e]);
    }
}

// ---------------- 2) weight repacks ----------------------------------------
__global__ void repackU_kernel(const float* __restrict__ Uw) {
    int idx = blockIdx.x * blockDim.x + threadIdx.x;   // 65536
    if (idx >= G4 * Dd) return;
    int n = idx >> 7, k = idx & 127;
    g_Uh[idx] = __float2half(Uw[k * G4 + n]);
}

__global__ void repackW_kernel(const float* __restrict__ lstm_W,
                               const float* __restrict__ Wq,
                               const float* __restrict__ Wk,
                               const float* __restrict__ Wv,
                               const float* __restrict__ Wo,
                               const float* __restrict__ W1) {
    int idx = blockIdx.x * blockDim.x + threadIdx.x;
    if (idx < Dd * G4) {
        g_Wr[idx] = to_tf32(lstm_W[idx]);
        return;
    }
    int j = idx - Dd * G4;
    if (j < Dd * 384) {
        int k = j / 384, n = j % 384;
        float v = (n < 128) ? Wq[k * Dd + n]
                : (n < 256) ? Wk[k * Dd + (n - 128)]
                            : Wv[k * Dd + (n - 256)];
        g_Wqkv[j] = to_tf32(v);
        return;
    }
    j -= Dd * 384;
    if (j < Dd * Dd) { g_Wor[j] = to_tf32(Wo[j]); return; }
    j -= Dd * Dd;
    if (j < UE * Dd) g_W1r[j] = to_tf32(W1[j]);
}

// ---------------- tf32 tensor-core GEMM: C[M,N]=A[M,K]@W[K,N] (+bias) -------
__global__ __launch_bounds__(256, 2) void gemm_tf32(
    const float* __restrict__ A, const float* __restrict__ W,
    const float* __restrict__ bias, float* __restrict__ C,
    int M, int N, int K) {
    __shared__ float As[128][36];
    __shared__ float Bs[32][136];
    int tid = threadIdx.x;
    int lane = tid & 31, warp = tid >> 5;
    int wm = warp >> 1, wn = warp & 1;
    int g = lane >> 2, tig = lane & 3;
    int m0 = blockIdx.y * 128, n0 = blockIdx.x * 128;

    float c[2][8][4];
#pragma unroll
    for (int i = 0; i < 2; i++)
#pragma unroll
        for (int j = 0; j < 8; j++)
#pragma unroll
            for (int l = 0; l < 4; l++) c[i][j][l] = 0.f;

    for (int k0 = 0; k0 < K; k0 += 32) {
        if (k0) __syncthreads();
#pragma unroll
        for (int i = 0; i < 4; i++) {
            int idx = tid + i * 256;
            int r = idx >> 3, c4 = (idx & 7) * 4;
            cp16(&As[r][c4], &A[(m0 + r) * K + k0 + c4]);
        }
#pragma unroll
        for (int i = 0; i < 4; i++) {
            int idx = tid + i * 256;
            int r = idx >> 5, c4 = (idx & 31) * 4;
            cp16(&Bs[r][c4], &W[(k0 + r) * N + n0 + c4]);
        }
        asm volatile("cp.async.commit_group;");
        asm volatile("cp.async.wait_group 0;");
        __syncthreads();

#pragma unroll
        for (int kk = 0; kk < 32; kk += 8) {
            uint32_t a[2][4], b[8][2];
#pragma unroll
            for (int mt = 0; mt < 2; mt++) {
                int mr = wm * 32 + mt * 16;
                a[mt][0] = __float_as_uint(As[mr + g][kk + tig]);
                a[mt][1] = __float_as_uint(As[mr + g + 8][kk + tig]);
                a[mt][2] = __float_as_uint(As[mr + g][kk + tig + 4]);
                a[mt][3] = __float_as_uint(As[mr + g + 8][kk + tig + 4]);
            }
#pragma unroll
            for (int nt = 0; nt < 8; nt++) {
                int nc = wn * 64 + nt * 8 + g;
                b[nt][0] = __float_as_uint(Bs[kk + tig][nc]);
                b[nt][1] = __float_as_uint(Bs[kk + tig + 4][nc]);
            }
#pragma unroll
            for (int mt = 0; mt < 2; mt++)
#pragma unroll
                for (int nt = 0; nt < 8; nt++)
                    mma_tf32(c[mt][nt], a[mt], b[nt]);
        }
    }

#pragma unroll
    for (int mt = 0; mt < 2; mt++) {
        int row = m0 + wm * 32 + mt * 16 + g;
#pragma unroll
        for (int nt = 0; nt < 8; nt++) {
            int col = n0 + wn * 64 + nt * 8 + 2 * tig;
            float bx = 0.f, by = 0.f;
            if (bias) { bx = bias[col]; by = bias[col + 1]; }
            float2 o0 = make_float2(c[mt][nt][0] + bx, c[mt][nt][1] + by);
            float2 o1 = make_float2(c[mt][nt][2] + bx, c[mt][nt][3] + by);
            *(float2*)&C[row * N + col] = o0;
            *(float2*)&C[(row + 8) * N + col] = o1;
        }
    }
}

// ---------------- 3) LSTM: fp16 mma, 16 warps (4/SMSP), pipelined xW --------
// 128 CTAs x 8 rows, 512 threads (16 warps). Warp w owns d-cols [w*8,w*8+8)
// across ALL 4 gates (B n-rows = gate*128 + w*8 + t... single n-tile/gate).
// U fragments = 64 regs/thread (32K regs/CTA total, no duplication). Per
// warp/step: 8 ldsm_x4 (A) + 32 mma. Each lane's acc c0/c1 = the 4 gate
// pre-activations of its 2 cells (row gid, cols w*8+2tig, +1) -> in-register
// epilogue. xW loads issued ONE STEP AHEAD (hidden under mma+epilogue of the
// previous step). h double-buffered -> 1 __syncthreads per step.
#define UT_STRIDE 136          // fp16 elems per Ut row (conflict-free ldmatrix)
#define HB_STRIDE 136
#define LSTM_ROWS 8
#define LSTM_SMEM_BYTES (G4 * UT_STRIDE * 2 + 2 * 16 * HB_STRIDE * 2)

__global__ __launch_bounds__(512, 1) void lstm_mma_kernel(
    const float* __restrict__ xW, float* __restrict__ hs) {
    extern __shared__ __align__(16) char smem_raw[];
    __half* Ut  = (__half*)smem_raw;                          // [512][136]
    __half* hb0 = (__half*)(smem_raw + G4 * UT_STRIDE * 2);   // [16][136]
    __half* hb1 = hb0 + 16 * HB_STRIDE;                       // [16][136]

    int tid = threadIdx.x;
    int lane = tid & 31, warp = tid >> 5;                     // warp 0..15
    int b0 = blockIdx.x * LSTM_ROWS;

    // ---- stage U^T into smem; zero BOTH h buffers (rows 8-15 stay 0) ----
    for (int i = tid; i < G4 * Dd / 8; i += 512) {            // 8192 16B chunks
        int n = i >> 4, c = (i & 15) * 8;
        cp16(&Ut[n * UT_STRIDE + c], &g_Uh[n * Dd + c]);
    }
    for (int i = tid; i < 2 * 16 * HB_STRIDE; i += 512) hb0[i] = __float2half(0.f);
    asm volatile("cp.async.commit_group;");
    asm volatile("cp.async.wait_group 0;");
    __syncthreads();

    // ---- ldmatrix A base addresses (both buffers) ----
    int arow = lane & 15;
    int akofs = (lane >> 4) * 8;
    uint32_t aAddr0 = (uint32_t)__cvta_generic_to_shared(hb0) +
                      (arow * HB_STRIDE + akofs) * 2;
    uint32_t aAddr1 = (uint32_t)__cvta_generic_to_shared(hb1) +
                      (arow * HB_STRIDE + akofs) * 2;

    // ---- preload U fragments: warp w, gate g -> n-rows g*128 + w*8 + bn ----
    uint32_t ut_base = (uint32_t)__cvta_generic_to_shared(Ut);
    int bn = lane & 7;
    int bkofs = ((lane >> 3) & 1) * 8;
    uint32_t bf[8][4][2];                                     // [kt][gate][2]
#pragma unroll
    for (int g = 0; g < 4; g++) {
        uint32_t base = ut_base +
            ((g * 128 + warp * 8 + bn) * UT_STRIDE + bkofs) * 2;
#pragma unroll
        for (int kt = 0; kt < 8; kt++)
            ldsm_x2(bf[kt][g][0], bf[kt][g][1], base + kt * 32);
    }

    int gid = lane >> 2, tig = lane & 3;
    int col0 = warp * 8 + 2 * tig;                            // this lane's 2 cells
    const float* xrow = xW + (size_t)((b0 + gid) * Ss) * G4 + col0;
    float* hsrow = hs + (size_t)((b0 + gid) * Ss) * Dd + col0;

    float cc0 = 0.f, cc1 = 0.f;
    float2 xg_c[4], xg_n[4];
#pragma unroll
    for (int g = 0; g < 4; g++) {                             // step 0 operand
        xg_c[g] = *(const float2*)&xrow[g * 128];
        xg_n[g] = xg_c[g];
    }

    int p = 0;
    for (int step = 0; step < Ss; step++) {
        // issue NEXT step's xW loads first (hidden under this step's compute)
        if (step + 1 < Ss) {
            const float* xb = xrow + (step + 1) * G4;
#pragma unroll
            for (int g = 0; g < 4; g++)
                xg_n[g] = *(const float2*)&xb[g * 128];
        }

        // ---- mma phase: z = h @ U for this warp's 8 cols x 4 gates ----
        float acc[4][4];
#pragma unroll
        for (int g = 0; g < 4; g++)
#pragma unroll
            for (int j = 0; j < 4; j++) acc[g][j] = 0.f;
        uint32_t aAddr = p ? aAddr1 : aAddr0;
#pragma unroll
        for (int kt = 0; kt < 8; kt++) {
            uint32_t a[4];
            ldsm_x4(a[0], a[1], a[2], a[3], aAddr + kt * 32);
#pragma unroll
            for (int g = 0; g < 4; g++)
                mma_f16(acc[g], a, bf[kt][g]);
        }

        // ---- in-register epilogue: 2 cells (row gid; c0/c1 live) ----
        float iv0 = sigm_mufu(acc[0][0] + xg_c[0].x);
        float iv1 = sigm_mufu(acc[0][1] + xg_c[0].y);
        float fv0 = sigm_mufu(acc[1][0] + xg_c[1].x);
        float fv1 = sigm_mufu(acc[1][1] + xg_c[1].y);
        float gv0 = tanh_mufu(acc[2][0] + xg_c[2].x);
        float gv1 = tanh_mufu(acc[2][1] + xg_c[2].y);
        float ov0 = sigm_mufu(acc[3][0] + xg_c[3].x);
        float ov1 = sigm_mufu(acc[3][1] + xg_c[3].y);
        cc0 = fv0 * cc0 + iv0 * gv0;
        cc1 = fv1 * cc1 + iv1 * gv1;
        float h0 = ov0 * tanh_mufu(cc0);
        float h1 = ov1 * tanh_mufu(cc1);

        // write h to the OTHER buffer; tf32 copy to global
        __half* hw = p ? hb0 : hb1;
        *(__half2*)&hw[gid * HB_STRIDE + col0] = __floats2half2_rn(h0, h1);
        *(float2*)&hsrow[step * Dd] = make_float2(to_tf32(h0), to_tf32(h1));
        __syncthreads();
        p ^= 1;
#pragma unroll
        for (int g = 0; g < 4; g++) xg_c[g] = xg_n[g];
    }
}

// ---------------- 4) MHA core: one block per (b, head) ----------------------
__global__ __launch_bounds__(128) void mha_kernel() {
    int bh = blockIdx.x;
    int b = bh >> 2, h = bh & 3;
    __shared__ float qs[Ss][Ee], ks[Ss][Ee], vs[Ss][Ee];
    __shared__ float sc[Ss][52];
    int t = threadIdx.x;
    for (int idx = t; idx < Ss * Ee; idx += 128) {
        int s = idx >> 5, e = idx & 31;
        int base = (b * Ss + s) * 384 + h * Ee + e;
        qs[s][e] = g_qkv[base];
        ks[s][e] = g_qkv[base + 128];
        vs[s][e] = g_qkv[base + 256];
    }
    __syncthreads();
    const float scale = 0.17677669529663687f;  // 1/sqrt(32)
    for (int idx = t; idx < Ss * Ss; idx += 128) {
        int r = idx / Ss, c = idx % Ss;
        float a = 0.f;
#pragma unroll
        for (int e = 0; e < Ee; e++) a += qs[r][e] * ks[c][e];
        sc[r][c] = a * scale;
    }
    __syncthreads();
    if (t < Ss) {
        float mx = -3.4e38f;
        for (int c = 0; c < Ss; c++) mx = fmaxf(mx, sc[t][c]);
        float sm = 0.f;
        for (int c = 0; c < Ss; c++) { float e = __expf(sc[t][c] - mx); sc[t][c] = e; sm += e; }
        float inv = 1.f / sm;
        for (int c = 0; c < Ss; c++) sc[t][c] *= inv;
    }
    __syncthreads();
    for (int idx = t; idx < Ss * Ee; idx += 128) {
        int s = idx >> 5, e = idx & 31;
        float a = 0.f;
        for (int c = 0; c < Ss; c++) a += sc[s][c] * vs[c][e];
        g_att[(b * Ss + s) * Dd + h * Ee + e] = to_tf32(a);
    }
}

// ---------------- 5) short-term attention pooling (parallel softmax) --------
__global__ __launch_bounds__(128) void shortpool_kernel() {
    int b = blockIdx.x;
    __shared__ float qv[Dd];
    __shared__ float sc[64];
    __shared__ float red4[4];
    int t = threadIdx.x;
    qv[t] = g_qvec[b * Dd + t];
    if (t >= Ss && t < 64) sc[t] = -3.4e38f;
    __syncthreads();
    if (t < Ss) {
        const float* row = &g_stm[(b * Ss + t) * Dd];
        float a = 0.f;
        for (int k = 0; k < Dd; k++) a += row[k] * qv[k];
        sc[t] = a;
    }
    __syncthreads();
    if (t < 64) {
        float v = sc[t];
#pragma unroll
        for (int ofs = 16; ofs >= 1; ofs >>= 1)
            v = fmaxf(v, __shfl_xor_sync(0xFFFFFFFFu, v, ofs));
        if ((t & 31) == 0) red4[t >> 5] = v;
    }
    __syncthreads();
    float mx = fmaxf(red4[0], red4[1]);
    float ev = (t < Ss) ? __expf(sc[t] - mx) : 0.f;
    if (t < 64) sc[t] = ev;
    __syncthreads();
    if (t < 64) {
        float v = sc[t];
#pragma unroll
        for (int ofs = 16; ofs >= 1; ofs >>= 1)
            v += __shfl_xor_sync(0xFFFFFFFFu, v, ofs);
        if ((t & 31) == 0) red4[2 + (t >> 5)] = v;
    }
    __syncthreads();
    float inv = 1.f / (red4[2] + red4[3]);
    float a = 0.f;
    for (int s = 0; s < Ss; s++) a += sc[s] * g_stm[(b * Ss + s) * Dd + t];
    g_short[b * Dd + t] = a * inv;
}

// ---------------- 6) long-term field attention (dedup mask) -----------------
__global__ __launch_bounds__(256) void longterm_kernel(const int* __restrict__ ltb,
                                                       const float* __restrict__ emb,
                                                       const float* __restrict__ Wt,
                                                       const float* __restrict__ bt) {
    int bi = blockIdx.x;
    int b = bi >> 2, fi = bi & 3;
    __shared__ int   ids[Ll];
    __shared__ float vecs[Ll][Ee];
    __shared__ float sc[Ll];
    __shared__ float uv[Ee];
    __shared__ float part[8][Ee];
    __shared__ float red[256];
    int t = threadIdx.x;
    if (t < Ll) ids[t] = ltb[(b * Ll + t) * Ff + fi];
    __syncthreads();
    for (int idx = t; idx < Ll * Ee; idx += 256) {
        int l = idx >> 5, e = idx & 31;
        vecs[l][e] = emb[ids[l] * Ee + e];
    }
    {
        int e = t & 31, g = t >> 5;
        float a = 0.f;
        for (int k = g * 32; k < g * 32 + 32; k++)
            a += g_user_e[b * UE + k] * Wt[(fi * UE + k) * Ee + e];
        part[g][e] = a;
    }
    __syncthreads();
    if (t < Ee) {
        float a = bt[fi * Ee + t];
        for (int g = 0; g < 8; g++) a += part[g][t];
        uv[t] = a;
    }
    __syncthreads();
    if (t < Ll) {
        int mid = ids[t];
        bool keep = true;
        for (int j = 0; j < t; j++) if (ids[j] == mid) { keep = false; break; }
        float a = 0.f;
#pragma unroll
        for (int e = 0; e < Ee; e++) a += vecs[t][e] * uv[e];
        sc[t] = keep ? a : NEGV;
    }
    __syncthreads();
    red[t] = (t < Ll) ? sc[t] : -3.4e38f;
    __syncthreads();
    for (int ofs = 128; ofs >= 1; ofs >>= 1) {
        if (t < ofs) red[t] = fmaxf(red[t], red[t + ofs]);
        __syncthreads();
    }
    float mx = red[0];
    __syncthreads();
    float ev = (t < Ll) ? __expf(sc[t] - mx) : 0.f;
    if (t < Ll) sc[t] = ev;
    red[t] = ev;
    __syncthreads();
    for (int ofs = 128; ofs >= 1; ofs >>= 1) {
        if (t < ofs) red[t] += red[t + ofs];
        __syncthreads();
    }
    float inv = 1.f / red[0];
    __syncthreads();
    {
        int e = t & 31, g = t >> 5;
        float a = 0.f;
        for (int l = g; l < Ll; l += 8) a += sc[l] * vecs[l][e];
        part[g][e] = a;
    }
    __syncthreads();
    if (t < Ee) {
        float a = 0.f;
        for (int g = 0; g < 8; g++) a += part[g][t];
        g_long[b * Dd + fi * Ee + t] = a * inv;
    }
}

// ---------------- 7) final gate + mix ---------------------------------------
__global__ __launch_bounds__(128) void gate_kernel(
    const float* __restrict__ Wu, const float* __restrict__ bu,
    const float* __restrict__ Wsg, const float* __restrict__ bsg,
    const float* __restrict__ Wl, const float* __restrict__ bl,
    float* __restrict__ out) {
    int b = blockIdx.x, d = threadIdx.x;
    __shared__ float ue[UE], sh[Dd], lg[Dd];
    ue[d] = g_user_e[b * UE + d];
    ue[d + 128] = g_user_e[b * UE + 128 + d];
    sh[d] = g_short[b * Dd + d];
    lg[d] = g_long[b * Dd + d];
    __syncthreads();
    float a = bu[d] + bsg[d] + bl[d];
    for (int k = 0; k < UE; k++) a += ue[k] * Wu[k * Dd + d];
    for (int k = 0; k < Dd; k++) a += sh[k] * Wsg[k * Dd + d] + lg[k] * Wl[k * Dd + d];
    float g = sigm(a);
    out[b * Dd + d] = (1.f - g) * lg[d] + g * sh[d];
}

// ---------------- host ------------------------------------------------------
static float* sym(const void* s) {
    void* p = nullptr;
    cudaGetSymbolAddress(&p, s);
    return (float*)p;
}

extern "C" void kernel_launch(void* const* d_in, const int* in_sizes, int n_in,
                              void* d_out, int out_size) {
    const int*   up     = (const int*)d_in[0];
    const int*   stb    = (const int*)d_in[1];
    const int*   ltb    = (const int*)d_in[2];
    const float* emb    = (const float*)d_in[3];
    const float* lstm_W = (const float*)d_in[4];
    const float* lstm_U = (const float*)d_in[5];
    const float* lstm_b = (const float*)d_in[6];
    const float* Wq     = (const float*)d_in[7];
    const float* Wk     = (const float*)d_in[8];
    const float* Wv     = (const float*)d_in[9];
    const float* Wo     = (const float*)d_in[10];
    const float* W1     = (const float*)d_in[11];
    const float* b1     = (const float*)d_in[12];
    const float* Wt     = (const float*)d_in[13];
    const float* bt     = (const float*)d_in[14];
    const float* Wu     = (const float*)d_in[15];
    const float* bu     = (const float*)d_in[16];
    const float* Wsg    = (const float*)d_in[17];
    const float* bsg    = (const float*)d_in[18];
    const float* Wl     = (const float*)d_in[19];
    const float* bl     = (const float*)d_in[20];
    float* out = (float*)d_out;

    float* p_user  = sym(g_user_e);
    float* p_usert = sym(g_user_t);
    float* p_stx   = sym(g_stx);
    float* p_xW    = sym(g_xW);
    float* p_hs    = sym(g_hs);
    float* p_qkv   = sym(g_qkv);
    float* p_att   = sym(g_att);
    float* p_stm   = sym(g_stm);
    float* p_qvec  = sym(g_qvec);
    float* p_Wr    = sym(g_Wr);
    float* p_Wqkv  = sym(g_Wqkv);
    float* p_Wor   = sym(g_Wor);
    float* p_W1r   = sym(g_W1r);

    const int MBS = Bb * Ss;  // 51200

    // idempotent, every call (no static guards)
    cudaFuncSetAttribute(lstm_mma_kernel,
                         cudaFuncAttributeMaxDynamicSharedMemorySize,
                         LSTM_SMEM_BYTES);

    // 1) gathers + weight repacks
    {
        int total = Bb * UE + Bb * Ss * Dd;
        gather_kernel<<<(total + 255) / 256, 256>>>(up, stb, emb);
        repackU_kernel<<<(G4 * Dd + 255) / 256, 256>>>(lstm_U);
        int wtotal = Dd * G4 + Dd * 384 + Dd * Dd + UE * Dd;
        repackW_kernel<<<(wtotal + 255) / 256, 256>>>(lstm_W, Wq, Wk, Wv, Wo, W1);
    }
    // 2) xW = stx @ lstm_W + b   (51200 x 512 x 128) tf32
    gemm_tf32<<<dim3(G4 / 128, MBS / 128), 256>>>(p_stx, p_Wr, lstm_b, p_xW, MBS, G4, Dd);
    // 3) LSTM recurrence: fp16 mma, 16 warps, reg-resident U, pipelined xW
    lstm_mma_kernel<<<Bb / LSTM_ROWS, 512, LSTM_SMEM_BYTES>>>(p_xW, p_hs);
    // 4) fused QKV projection (51200 x 384 x 128) tf32
    gemm_tf32<<<dim3(384 / 128, MBS / 128), 256>>>(p_hs, p_Wqkv, nullptr, p_qkv, MBS, 384, Dd);
    // 5) attention core + output projection
    mha_kernel<<<Bb * Ff, 128>>>();
    gemm_tf32<<<dim3(Dd / 128, MBS / 128), 256>>>(p_att, p_Wor, nullptr, p_stm, MBS, Dd, Dd);
    // 6) pooling query (tf32) + short-term pooling
    gemm_tf32<<<dim3(Dd / 128, Bb / 128), 256>>>(p_usert, p_W1r, b1, p_qvec, Bb, Dd, UE);
    shortpool_kernel<<<Bb, 128>>>();
    // 7) long-term field attention
    longterm_kernel<<<Bb * Ff, 256>>>(ltb, emb, Wt, bt);
    // 8) gate + mix -> out
    gate_kernel<<<Bb, 128>>>(Wu, bu, Wsg, bsg, Wl, bl, out);
}